// round 1
// baseline (speedup 1.0000x reference)
#include <cuda_runtime.h>
#include <cstdint>

#define N_NODES   10000
#define E_EDGES   160000
#define D_DIM     512
#define EDGE_DIM  128
#define L_LAYERS  3
#define LN_EPS    1e-5f

// ---------------- scratch (device globals; no runtime alloc allowed) ----------------
__device__ __align__(16) float g_P  [(size_t)E_EDGES * D_DIM];  // edge messages (327MB)
__device__ __align__(16) float g_agg[(size_t)N_NODES * D_DIM];
__device__ __align__(16) float g_h  [(size_t)N_NODES * D_DIM];
__device__ __align__(16) float g_t  [(size_t)N_NODES * D_DIM];
__device__ __align__(16) float g_g  [(size_t)N_NODES * D_DIM];
__device__ int g_is64;

// ---------------- edge_index dtype detection ----------------
// If the buffer really holds int64 indices, every int64-interpreted value is in [0, N).
// If it holds int32, pairs combine into huge values -> flag cleared.
__global__ void set_flag_kernel() { g_is64 = 1; }

__global__ void detect_kernel(const long long* __restrict__ ei) {
    int idx = blockIdx.x * blockDim.x + threadIdx.x;
    bool bad = false;
    for (int i = idx; i < E_EDGES; i += gridDim.x * blockDim.x) {
        long long v = ei[i];                 // always within the smaller (int32) buffer size
        if (v < 0 || v >= N_NODES) bad = true;
    }
    if (__syncthreads_or(bad)) {
        if (threadIdx.x == 0) g_is64 = 0;
    }
}

// ---------------- simple vector copy ----------------
__global__ void copy_kernel(const float4* __restrict__ in, float4* __restrict__ out, int n4) {
    int i = blockIdx.x * blockDim.x + threadIdx.x;
    if (i < n4) out[i] = in[i];
}

// ---------------- agg = (1+eps[l]) * h ----------------
__global__ void scale_init_kernel(const float4* __restrict__ h, const float* __restrict__ eps,
                                  int l, float4* __restrict__ agg, int n4) {
    int i = blockIdx.x * blockDim.x + threadIdx.x;
    if (i >= n4) return;
    float s = 1.0f + eps[l];
    float4 v = h[i];
    v.x *= s; v.y *= s; v.z *= s; v.w *= s;
    agg[i] = v;
}

// ---------------- edge scatter: agg[dst] += relu(h[src] + P[e]) ----------------
// one warp per edge; 512 cols = 128 float4 -> 4 float4 per lane
__global__ void __launch_bounds__(256) edge_scatter_kernel(const float* __restrict__ h,
                                                           const void* __restrict__ ei_raw,
                                                           float* __restrict__ agg) {
    int e = blockIdx.x * 8 + (threadIdx.x >> 5);
    int lane = threadIdx.x & 31;
    if (e >= E_EDGES) return;
    long long s, d;
    if (g_is64) {
        const long long* p = (const long long*)ei_raw;
        s = p[e]; d = p[E_EDGES + e];
    } else {
        const int* p = (const int*)ei_raw;
        s = p[e]; d = p[E_EDGES + e];
    }
    const float4* hs = (const float4*)(h + (size_t)s * D_DIM);
    const float4* pp = (const float4*)(g_P + (size_t)e * D_DIM);
    float* ag = agg + (size_t)d * D_DIM;
#pragma unroll
    for (int j = 0; j < 4; j++) {
        int c = lane + j * 32;            // float4 index within row
        float4 hv = hs[c];
        float4 pv = pp[c];
        float m;
        m = hv.x + pv.x; if (m > 0.f) atomicAdd(&ag[c * 4 + 0], m);
        m = hv.y + pv.y; if (m > 0.f) atomicAdd(&ag[c * 4 + 1], m);
        m = hv.z + pv.z; if (m > 0.f) atomicAdd(&ag[c * 4 + 2], m);
        m = hv.w + pv.w; if (m > 0.f) atomicAdd(&ag[c * 4 + 3], m);
    }
}

// ---------------- SGEMM: C[M,N] = A[M,K] @ B[K,N] + bias (optional relu) ----------------
// BM=128, BN=128, BK=8, 256 threads, 8x8 per-thread tile. N must be a multiple of 128,
// K a multiple of 8 (true for all call sites: N=512, K in {128,512}). M bounds-guarded.
__global__ void __launch_bounds__(256) sgemm_kernel(const float* __restrict__ A,
                                                    const float* __restrict__ B,
                                                    const float* __restrict__ bias,
                                                    float* __restrict__ C,
                                                    int M, int N, int K, int doRelu) {
    const int BM = 128, BN = 128, BK = 8;
    __shared__ float As[BK][BM];
    __shared__ float Bs[BK][BN];

    int tid  = threadIdx.x;
    int brow = blockIdx.y * BM;
    int bcol = blockIdx.x * BN;
    int trow = (tid / 16) * 8;
    int tcol = (tid % 16) * 8;

    float acc[8][8];
#pragma unroll
    for (int i = 0; i < 8; i++)
#pragma unroll
        for (int j = 0; j < 8; j++) acc[i][j] = 0.f;

    int aRow = tid >> 1;            // 0..127
    int aCol = (tid & 1) * 4;       // 0 or 4
    int bRow = tid >> 5;            // 0..7
    int bCol = (tid & 31) * 4;      // 0..124

    bool aValid = (brow + aRow) < M;
    const float* Aptr = A + (size_t)(brow + aRow) * K + aCol;
    const float* Bptr = B + (size_t)bRow * N + bcol + bCol;

    for (int k0 = 0; k0 < K; k0 += BK) {
        float4 av = aValid ? *(const float4*)(Aptr + k0) : make_float4(0.f, 0.f, 0.f, 0.f);
        As[aCol + 0][aRow] = av.x;
        As[aCol + 1][aRow] = av.y;
        As[aCol + 2][aRow] = av.z;
        As[aCol + 3][aRow] = av.w;
        *(float4*)&Bs[bRow][bCol] = *(const float4*)(Bptr + (size_t)k0 * N);
        __syncthreads();
#pragma unroll
        for (int kk = 0; kk < BK; kk++) {
            float a[8], b[8];
            *(float4*)&a[0] = *(const float4*)&As[kk][trow];
            *(float4*)&a[4] = *(const float4*)&As[kk][trow + 4];
            *(float4*)&b[0] = *(const float4*)&Bs[kk][tcol];
            *(float4*)&b[4] = *(const float4*)&Bs[kk][tcol + 4];
#pragma unroll
            for (int i = 0; i < 8; i++)
#pragma unroll
                for (int j = 0; j < 8; j++) acc[i][j] += a[i] * b[j];
        }
        __syncthreads();
    }

#pragma unroll
    for (int i = 0; i < 8; i++) {
        int row = brow + trow + i;
        if (row < M) {
#pragma unroll
            for (int j = 0; j < 8; j += 4) {
                int col = bcol + tcol + j;
                float4 v;
                v.x = acc[i][j + 0] + bias[col + 0];
                v.y = acc[i][j + 1] + bias[col + 1];
                v.z = acc[i][j + 2] + bias[col + 2];
                v.w = acc[i][j + 3] + bias[col + 3];
                if (doRelu) {
                    v.x = fmaxf(v.x, 0.f); v.y = fmaxf(v.y, 0.f);
                    v.z = fmaxf(v.z, 0.f); v.w = fmaxf(v.w, 0.f);
                }
                *(float4*)&C[(size_t)row * N + col] = v;
            }
        }
    }
}

// ---------------- LayerNorm: out = (g-mu)*rsqrt(var+eps)*gamma + beta ----------------
// one block (128 threads) per row; each thread owns one float4 (512 = 128*4)
__global__ void __launch_bounds__(128) layernorm_kernel(const float* __restrict__ g,
                                                        const float* __restrict__ gamma,
                                                        const float* __restrict__ beta,
                                                        float* __restrict__ out) {
    int row = blockIdx.x;
    int t = threadIdx.x;
    const float4* gp = (const float4*)(g + (size_t)row * D_DIM);
    float4 v = gp[t];
    float s  = v.x + v.y + v.z + v.w;
    float sq = v.x * v.x + v.y * v.y + v.z * v.z + v.w * v.w;
#pragma unroll
    for (int o = 16; o > 0; o >>= 1) {
        s  += __shfl_xor_sync(0xffffffffu, s, o);
        sq += __shfl_xor_sync(0xffffffffu, sq, o);
    }
    __shared__ float red[8];
    int w = t >> 5;
    if ((t & 31) == 0) { red[w] = s; red[4 + w] = sq; }
    __syncthreads();
    s  = red[0] + red[1] + red[2] + red[3];
    sq = red[4] + red[5] + red[6] + red[7];
    float mu  = s * (1.0f / D_DIM);
    float var = sq * (1.0f / D_DIM) - mu * mu;
    float inv = rsqrtf(var + LN_EPS);
    float4 ga = *(const float4*)(gamma + t * 4);
    float4 be = *(const float4*)(beta + t * 4);
    float4 o;
    o.x = (v.x - mu) * inv * ga.x + be.x;
    o.y = (v.y - mu) * inv * ga.y + be.y;
    o.z = (v.z - mu) * inv * ga.z + be.z;
    o.w = (v.w - mu) * inv * ga.w + be.w;
    ((float4*)(out + (size_t)row * D_DIM))[t] = o;
}

// ---------------- launch ----------------
extern "C" void kernel_launch(void* const* d_in, const int* in_sizes, int n_in,
                              void* d_out, int out_size) {
    const float*     x     = (const float*)d_in[0];
    const void*      ei    = d_in[1];                 // int64 or int32 (detected on device)
    const float*     ea    = (const float*)d_in[2];
    const float*     We    = (const float*)d_in[3];
    const float*     be    = (const float*)d_in[4];
    const float*     eps   = (const float*)d_in[5];
    const float*     W1    = (const float*)d_in[6];
    const float*     b1    = (const float*)d_in[7];
    const float*     W2    = (const float*)d_in[8];
    const float*     b2    = (const float*)d_in[9];
    const float*     gamma = (const float*)d_in[10];
    const float*     beta  = (const float*)d_in[11];
    const float*     Wf    = (const float*)d_in[12];
    const float*     bf    = (const float*)d_in[13];
    float* out = (float*)d_out;

    float *P, *agg, *h, *t, *gg;
    cudaGetSymbolAddress((void**)&P,   g_P);
    cudaGetSymbolAddress((void**)&agg, g_agg);
    cudaGetSymbolAddress((void**)&h,   g_h);
    cudaGetSymbolAddress((void**)&t,   g_t);
    cudaGetSymbolAddress((void**)&gg,  g_g);

    // dtype detection for edge_index
    set_flag_kernel<<<1, 1>>>();
    detect_kernel<<<64, 256>>>((const long long*)ei);

    const int n4 = N_NODES * D_DIM / 4;
    copy_kernel<<<(n4 + 255) / 256, 256>>>((const float4*)x, (float4*)h, n4);

    dim3 gEdge(D_DIM / 128, E_EDGES / 128);           // (4, 1250)
    dim3 gNode(D_DIM / 128, (N_NODES + 127) / 128);   // (4, 79)

    for (int l = 0; l < L_LAYERS; l++) {
        // P = edge_attr @ We[l] + be[l]
        sgemm_kernel<<<gEdge, 256>>>(ea, We + (size_t)l * EDGE_DIM * D_DIM,
                                     be + (size_t)l * D_DIM, P,
                                     E_EDGES, D_DIM, EDGE_DIM, 0);
        // agg = (1+eps)*h
        scale_init_kernel<<<(n4 + 255) / 256, 256>>>((const float4*)h, eps, l, (float4*)agg, n4);
        // agg[dst] += relu(h[src] + P[e])
        edge_scatter_kernel<<<E_EDGES / 8, 256>>>(h, ei, agg);
        // t = relu(agg @ W1 + b1)
        sgemm_kernel<<<gNode, 256>>>(agg, W1 + (size_t)l * D_DIM * D_DIM,
                                     b1 + (size_t)l * D_DIM, t,
                                     N_NODES, D_DIM, D_DIM, 1);
        // gg = relu(t @ W2 + b2)        (relu(g) applied before LN)
        sgemm_kernel<<<gNode, 256>>>(t, W2 + (size_t)l * D_DIM * D_DIM,
                                     b2 + (size_t)l * D_DIM, gg,
                                     N_NODES, D_DIM, D_DIM, 1);
        // h = LayerNorm(gg)*gamma + beta
        layernorm_kernel<<<N_NODES, 128>>>(gg, gamma + (size_t)l * D_DIM,
                                           beta + (size_t)l * D_DIM, h);
    }
    // out = h @ Wf + bf
    sgemm_kernel<<<gNode, 256>>>(h, Wf, bf, out, N_NODES, D_DIM, D_DIM, 0);
}

// round 2
// speedup vs baseline: 1.1895x; 1.1895x over previous
#include <cuda_runtime.h>
#include <cstdint>

#define N_NODES   10000
#define E_EDGES   160000
#define D_DIM     512
#define EDGE_DIM  128
#define L_LAYERS  3
#define LN_EPS    1e-5f

// ---------------- scratch (device globals; no runtime alloc allowed) ----------------
__device__ __align__(16) float g_agg[(size_t)N_NODES * D_DIM];
__device__ __align__(16) float g_h  [(size_t)N_NODES * D_DIM];
__device__ __align__(16) float g_t  [(size_t)N_NODES * D_DIM];
__device__ __align__(16) float g_g  [(size_t)N_NODES * D_DIM];
__device__ int g_pos[N_NODES];          // counts -> offsets -> scatter cursor
__device__ int g_perm[E_EDGES];         // sorted-order -> original edge id
__device__ int g_sortedSrc[E_EDGES];
__device__ int g_sortedDst[E_EDGES];
__device__ int g_is64;

// ---------------- edge_index dtype detection ----------------
__global__ void set_flag_kernel() { g_is64 = 1; }

__global__ void detect_kernel(const long long* __restrict__ ei) {
    int idx = blockIdx.x * blockDim.x + threadIdx.x;
    bool bad = false;
    for (int i = idx; i < E_EDGES; i += gridDim.x * blockDim.x) {
        long long v = ei[i];
        if (v < 0 || v >= N_NODES) bad = true;
    }
    if (__syncthreads_or(bad)) {
        if (threadIdx.x == 0) g_is64 = 0;
    }
}

__device__ __forceinline__ void get_edge(const void* ei, int e, int& s, int& d) {
    if (g_is64) {
        const long long* p = (const long long*)ei;
        s = (int)p[e]; d = (int)p[E_EDGES + e];
    } else {
        const int* p = (const int*)ei;
        s = p[e]; d = p[E_EDGES + e];
    }
}

// ---------------- counting sort of edges by dst ----------------
__global__ void zero_pos_kernel() {
    int i = blockIdx.x * blockDim.x + threadIdx.x;
    if (i < N_NODES) g_pos[i] = 0;
}

__global__ void count_kernel(const void* __restrict__ ei) {
    int e = blockIdx.x * blockDim.x + threadIdx.x;
    if (e >= E_EDGES) return;
    int s, d; get_edge(ei, e, s, d);
    atomicAdd(&g_pos[d], 1);
}

// single-block exclusive scan over g_pos (in place): counts -> start offsets
__global__ void __launch_bounds__(1024) scan_kernel() {
    const int T = 1024;
    const int C = (N_NODES + T - 1) / T;   // 10
    __shared__ int sA[T], sB[T];
    int t = threadIdx.x;
    int base = t * C;
    int local[C];
    int sum = 0;
#pragma unroll
    for (int c = 0; c < C; c++) {
        int i = base + c;
        local[c] = (i < N_NODES) ? g_pos[i] : 0;
        sum += local[c];
    }
    sA[t] = sum;
    __syncthreads();
    int* cur = sA; int* nxt = sB;
    for (int off = 1; off < T; off <<= 1) {
        int v = cur[t];
        if (t >= off) v += cur[t - off];
        nxt[t] = v;
        __syncthreads();
        int* tmp = cur; cur = nxt; nxt = tmp;
    }
    int running = (t > 0) ? cur[t - 1] : 0;   // exclusive prefix of this chunk
#pragma unroll
    for (int c = 0; c < C; c++) {
        int i = base + c;
        if (i < N_NODES) g_pos[i] = running;
        running += local[c];
    }
}

__global__ void scatter_sort_kernel(const void* __restrict__ ei) {
    int e = blockIdx.x * blockDim.x + threadIdx.x;
    if (e >= E_EDGES) return;
    int s, d; get_edge(ei, e, s, d);
    int pos = atomicAdd(&g_pos[d], 1);
    g_perm[pos] = e;
    g_sortedSrc[pos] = s;
    g_sortedDst[pos] = d;
}

// ---------------- agg = (1+eps[l]) * h ----------------
__global__ void scale_init_kernel(const float4* __restrict__ h, const float* __restrict__ eps,
                                  int l, float4* __restrict__ agg, int n4) {
    int i = blockIdx.x * blockDim.x + threadIdx.x;
    if (i >= n4) return;
    float s = 1.0f + eps[l];
    float4 v = h[i];
    v.x *= s; v.y *= s; v.z *= s; v.w *= s;
    agg[i] = v;
}

// ---------------- fused edge GEMM + gather + relu + run-combined scatter ----------------
// Computes (for a 128-edge x 128-col tile over sorted edges):
//   m = relu( edge_attr[perm[r]] @ We + be + h[sortedSrc[r]] )
//   agg[sortedDst[r]] += m    (runs of equal dst combined in registers before atomics)
// K = EDGE_DIM = 128, BK = 16.
__global__ void __launch_bounds__(256) edge_fused_kernel(const float* __restrict__ EA,
                                                         const float* __restrict__ B,   // We[l] [128,512]
                                                         const float* __restrict__ bias,// be[l]
                                                         const float* __restrict__ h,
                                                         float* __restrict__ agg) {
    const int BK = 16;
    __shared__ float As[BK][128];
    __shared__ float Bs[BK][128];

    int tid  = threadIdx.x;
    int brow = blockIdx.y * 128;      // edge-tile base (sorted order)
    int bcol = blockIdx.x * 128;      // column-tile base
    int trow = (tid / 16) * 8;
    int tcol = (tid % 16) * 8;

    float acc[8][8];
#pragma unroll
    for (int i = 0; i < 8; i++)
#pragma unroll
        for (int j = 0; j < 8; j++) acc[i][j] = 0.f;

    int aRow = tid >> 1;                 // 0..127
    int aCol = (tid & 1) * 8;            // 0 or 8
    int bRow = tid >> 4;                 // 0..15
    int bCol = (tid & 15) * 8;           // 0..120

    int eid = g_perm[brow + aRow];       // gather row
    const float* Aptr = EA + (size_t)eid * EDGE_DIM + aCol;
    const float* Bptr = B + (size_t)bRow * D_DIM + bcol + bCol;

    for (int k0 = 0; k0 < EDGE_DIM; k0 += BK) {
        float4 a0 = *(const float4*)(Aptr + k0);
        float4 a1 = *(const float4*)(Aptr + k0 + 4);
        As[aCol + 0][aRow] = a0.x; As[aCol + 1][aRow] = a0.y;
        As[aCol + 2][aRow] = a0.z; As[aCol + 3][aRow] = a0.w;
        As[aCol + 4][aRow] = a1.x; As[aCol + 5][aRow] = a1.y;
        As[aCol + 6][aRow] = a1.z; As[aCol + 7][aRow] = a1.w;
        const float* bp = Bptr + (size_t)k0 * D_DIM;
        *(float4*)&Bs[bRow][bCol]     = *(const float4*)(bp);
        *(float4*)&Bs[bRow][bCol + 4] = *(const float4*)(bp + 4);
        __syncthreads();
#pragma unroll
        for (int kk = 0; kk < BK; kk++) {
            float a[8], b[8];
            *(float4*)&a[0] = *(const float4*)&As[kk][trow];
            *(float4*)&a[4] = *(const float4*)&As[kk][trow + 4];
            *(float4*)&b[0] = *(const float4*)&Bs[kk][tcol];
            *(float4*)&b[4] = *(const float4*)&Bs[kk][tcol + 4];
#pragma unroll
            for (int i = 0; i < 8; i++)
#pragma unroll
                for (int j = 0; j < 8; j++) acc[i][j] += a[i] * b[j];
        }
        __syncthreads();
    }

    // epilogue: bias + h[src] + relu, run-combine by dst, atomic flush
    int colg = bcol + tcol;
    float bv[8];
    *(float4*)&bv[0] = *(const float4*)(bias + colg);
    *(float4*)&bv[4] = *(const float4*)(bias + colg + 4);

    float run[8];
    int prevDst = -1;
#pragma unroll
    for (int i = 0; i < 8; i++) {
        int r = brow + trow + i;
        int s = g_sortedSrc[r];
        int d = g_sortedDst[r];
        const float4* hp = (const float4*)(h + (size_t)s * D_DIM + colg);
        float4 h0 = hp[0], h1 = hp[1];
        float m[8];
        m[0] = fmaxf(acc[i][0] + bv[0] + h0.x, 0.f);
        m[1] = fmaxf(acc[i][1] + bv[1] + h0.y, 0.f);
        m[2] = fmaxf(acc[i][2] + bv[2] + h0.z, 0.f);
        m[3] = fmaxf(acc[i][3] + bv[3] + h0.w, 0.f);
        m[4] = fmaxf(acc[i][4] + bv[4] + h1.x, 0.f);
        m[5] = fmaxf(acc[i][5] + bv[5] + h1.y, 0.f);
        m[6] = fmaxf(acc[i][6] + bv[6] + h1.z, 0.f);
        m[7] = fmaxf(acc[i][7] + bv[7] + h1.w, 0.f);
        if (d != prevDst) {
            if (prevDst >= 0) {
                float* ap = agg + (size_t)prevDst * D_DIM + colg;
#pragma unroll
                for (int j = 0; j < 8; j++)
                    if (run[j] != 0.f) atomicAdd(&ap[j], run[j]);
            }
#pragma unroll
            for (int j = 0; j < 8; j++) run[j] = m[j];
            prevDst = d;
        } else {
#pragma unroll
            for (int j = 0; j < 8; j++) run[j] += m[j];
        }
    }
    if (prevDst >= 0) {
        float* ap = agg + (size_t)prevDst * D_DIM + colg;
#pragma unroll
        for (int j = 0; j < 8; j++)
            if (run[j] != 0.f) atomicAdd(&ap[j], run[j]);
    }
}

// ---------------- SGEMM (BK=16): C = A@B + bias (optional relu) ----------------
// N multiple of 128, K multiple of 16. M bounds-guarded.
__global__ void __launch_bounds__(256) sgemm_kernel(const float* __restrict__ A,
                                                    const float* __restrict__ B,
                                                    const float* __restrict__ bias,
                                                    float* __restrict__ C,
                                                    int M, int N, int K, int doRelu) {
    const int BK = 16;
    __shared__ float As[BK][128];
    __shared__ float Bs[BK][128];

    int tid  = threadIdx.x;
    int brow = blockIdx.y * 128;
    int bcol = blockIdx.x * 128;
    int trow = (tid / 16) * 8;
    int tcol = (tid % 16) * 8;

    float acc[8][8];
#pragma unroll
    for (int i = 0; i < 8; i++)
#pragma unroll
        for (int j = 0; j < 8; j++) acc[i][j] = 0.f;

    int aRow = tid >> 1;
    int aCol = (tid & 1) * 8;
    int bRow = tid >> 4;
    int bCol = (tid & 15) * 8;

    bool aValid = (brow + aRow) < M;
    const float* Aptr = A + (size_t)(brow + aRow) * K + aCol;
    const float* Bptr = B + (size_t)bRow * N + bcol + bCol;

    for (int k0 = 0; k0 < K; k0 += BK) {
        float4 a0, a1;
        if (aValid) {
            a0 = *(const float4*)(Aptr + k0);
            a1 = *(const float4*)(Aptr + k0 + 4);
        } else {
            a0 = make_float4(0.f, 0.f, 0.f, 0.f);
            a1 = a0;
        }
        As[aCol + 0][aRow] = a0.x; As[aCol + 1][aRow] = a0.y;
        As[aCol + 2][aRow] = a0.z; As[aCol + 3][aRow] = a0.w;
        As[aCol + 4][aRow] = a1.x; As[aCol + 5][aRow] = a1.y;
        As[aCol + 6][aRow] = a1.z; As[aCol + 7][aRow] = a1.w;
        const float* bp = Bptr + (size_t)k0 * N;
        *(float4*)&Bs[bRow][bCol]     = *(const float4*)(bp);
        *(float4*)&Bs[bRow][bCol + 4] = *(const float4*)(bp + 4);
        __syncthreads();
#pragma unroll
        for (int kk = 0; kk < BK; kk++) {
            float a[8], b[8];
            *(float4*)&a[0] = *(const float4*)&As[kk][trow];
            *(float4*)&a[4] = *(const float4*)&As[kk][trow + 4];
            *(float4*)&b[0] = *(const float4*)&Bs[kk][tcol];
            *(float4*)&b[4] = *(const float4*)&Bs[kk][tcol + 4];
#pragma unroll
            for (int i = 0; i < 8; i++)
#pragma unroll
                for (int j = 0; j < 8; j++) acc[i][j] += a[i] * b[j];
        }
        __syncthreads();
    }

#pragma unroll
    for (int i = 0; i < 8; i++) {
        int row = brow + trow + i;
        if (row < M) {
#pragma unroll
            for (int j = 0; j < 8; j += 4) {
                int col = bcol + tcol + j;
                float4 v;
                v.x = acc[i][j + 0] + bias[col + 0];
                v.y = acc[i][j + 1] + bias[col + 1];
                v.z = acc[i][j + 2] + bias[col + 2];
                v.w = acc[i][j + 3] + bias[col + 3];
                if (doRelu) {
                    v.x = fmaxf(v.x, 0.f); v.y = fmaxf(v.y, 0.f);
                    v.z = fmaxf(v.z, 0.f); v.w = fmaxf(v.w, 0.f);
                }
                *(float4*)&C[(size_t)row * N + col] = v;
            }
        }
    }
}

// ---------------- LayerNorm ----------------
__global__ void __launch_bounds__(128) layernorm_kernel(const float* __restrict__ g,
                                                        const float* __restrict__ gamma,
                                                        const float* __restrict__ beta,
                                                        float* __restrict__ out) {
    int row = blockIdx.x;
    int t = threadIdx.x;
    const float4* gp = (const float4*)(g + (size_t)row * D_DIM);
    float4 v = gp[t];
    float s  = v.x + v.y + v.z + v.w;
    float sq = v.x * v.x + v.y * v.y + v.z * v.z + v.w * v.w;
#pragma unroll
    for (int o = 16; o > 0; o >>= 1) {
        s  += __shfl_xor_sync(0xffffffffu, s, o);
        sq += __shfl_xor_sync(0xffffffffu, sq, o);
    }
    __shared__ float red[8];
    int w = t >> 5;
    if ((t & 31) == 0) { red[w] = s; red[4 + w] = sq; }
    __syncthreads();
    s  = red[0] + red[1] + red[2] + red[3];
    sq = red[4] + red[5] + red[6] + red[7];
    float mu  = s * (1.0f / D_DIM);
    float var = sq * (1.0f / D_DIM) - mu * mu;
    float inv = rsqrtf(var + LN_EPS);
    float4 ga = *(const float4*)(gamma + t * 4);
    float4 be = *(const float4*)(beta + t * 4);
    float4 o;
    o.x = (v.x - mu) * inv * ga.x + be.x;
    o.y = (v.y - mu) * inv * ga.y + be.y;
    o.z = (v.z - mu) * inv * ga.z + be.z;
    o.w = (v.w - mu) * inv * ga.w + be.w;
    ((float4*)(out + (size_t)row * D_DIM))[t] = o;
}

// ---------------- launch ----------------
extern "C" void kernel_launch(void* const* d_in, const int* in_sizes, int n_in,
                              void* d_out, int out_size) {
    const float*     x     = (const float*)d_in[0];
    const void*      ei    = d_in[1];
    const float*     ea    = (const float*)d_in[2];
    const float*     We    = (const float*)d_in[3];
    const float*     be    = (const float*)d_in[4];
    const float*     eps   = (const float*)d_in[5];
    const float*     W1    = (const float*)d_in[6];
    const float*     b1    = (const float*)d_in[7];
    const float*     W2    = (const float*)d_in[8];
    const float*     b2    = (const float*)d_in[9];
    const float*     gamma = (const float*)d_in[10];
    const float*     beta  = (const float*)d_in[11];
    const float*     Wf    = (const float*)d_in[12];
    const float*     bf    = (const float*)d_in[13];
    float* out = (float*)d_out;

    float *agg, *h, *t, *gg;
    cudaGetSymbolAddress((void**)&agg, g_agg);
    cudaGetSymbolAddress((void**)&h,   g_h);
    cudaGetSymbolAddress((void**)&t,   g_t);
    cudaGetSymbolAddress((void**)&gg,  g_g);

    // dtype detection + counting sort of edges by dst (once; inputs constant)
    set_flag_kernel<<<1, 1>>>();
    detect_kernel<<<64, 256>>>((const long long*)ei);
    zero_pos_kernel<<<(N_NODES + 255) / 256, 256>>>();
    count_kernel<<<(E_EDGES + 255) / 256, 256>>>(ei);
    scan_kernel<<<1, 1024>>>();
    scatter_sort_kernel<<<(E_EDGES + 255) / 256, 256>>>(ei);

    const int n4 = N_NODES * D_DIM / 4;
    dim3 gEdge(D_DIM / 128, E_EDGES / 128);           // (4, 1250)
    dim3 gNode(D_DIM / 128, (N_NODES + 127) / 128);   // (4, 79)

    for (int l = 0; l < L_LAYERS; l++) {
        const float* hCur = (l == 0) ? x : h;
        // agg = (1+eps)*h
        scale_init_kernel<<<(n4 + 255) / 256, 256>>>((const float4*)hCur, eps, l, (float4*)agg, n4);
        // agg[dst] += relu(edge_attr@We + be + h[src])   (fused, sorted, run-combined)
        edge_fused_kernel<<<gEdge, 256>>>(ea, We + (size_t)l * EDGE_DIM * D_DIM,
                                          be + (size_t)l * D_DIM, hCur, agg);
        // t = relu(agg @ W1 + b1)
        sgemm_kernel<<<gNode, 256>>>(agg, W1 + (size_t)l * D_DIM * D_DIM,
                                     b1 + (size_t)l * D_DIM, t,
                                     N_NODES, D_DIM, D_DIM, 1);
        // gg = relu(t @ W2 + b2)
        sgemm_kernel<<<gNode, 256>>>(t, W2 + (size_t)l * D_DIM * D_DIM,
                                     b2 + (size_t)l * D_DIM, gg,
                                     N_NODES, D_DIM, D_DIM, 1);
        // h = LayerNorm(gg)
        layernorm_kernel<<<N_NODES, 128>>>(gg, gamma + (size_t)l * D_DIM,
                                           beta + (size_t)l * D_DIM, h);
    }
    sgemm_kernel<<<gNode, 256>>>(h, Wf, bf, out, N_NODES, D_DIM, D_DIM, 0);
}

// round 4
// speedup vs baseline: 1.3067x; 1.0985x over previous
#include <cuda_runtime.h>
#include <cstdint>

#define N_NODES   10000
#define E_EDGES   160000
#define D_DIM     512
#define EDGE_DIM  128
#define L_LAYERS  3
#define LN_EPS    1e-5f

// ---------------- scratch (device globals) ----------------
__device__ __align__(16) float g_agg[(size_t)N_NODES * D_DIM];
__device__ __align__(16) float g_h  [(size_t)N_NODES * D_DIM];
__device__ __align__(16) float g_t  [(size_t)N_NODES * D_DIM];
__device__ __align__(16) float g_g  [(size_t)N_NODES * D_DIM];
__device__ int g_pos[N_NODES];
__device__ int g_perm[E_EDGES];
__device__ int g_sortedSrc[E_EDGES];
__device__ int g_sortedDst[E_EDGES];
__device__ int g_is64;

// ---------------- helpers ----------------
__device__ __forceinline__ void tf32_split(float x, float& hi, float& lo) {
    uint32_t u;
    asm("cvt.rna.tf32.f32 %0, %1;" : "=r"(u) : "f"(x));
    hi = __uint_as_float(u);
    float r = x - hi;
    asm("cvt.rna.tf32.f32 %0, %1;" : "=r"(u) : "f"(r));
    lo = __uint_as_float(u);
}
__device__ __forceinline__ void mma_tf32(float* c, const float* a, float b0, float b1) {
    asm volatile("mma.sync.aligned.m16n8k8.row.col.f32.tf32.tf32.f32 "
        "{%0,%1,%2,%3}, {%4,%5,%6,%7}, {%8,%9}, {%0,%1,%2,%3};"
        : "+f"(c[0]), "+f"(c[1]), "+f"(c[2]), "+f"(c[3])
        : "r"(__float_as_uint(a[0])), "r"(__float_as_uint(a[1])),
          "r"(__float_as_uint(a[2])), "r"(__float_as_uint(a[3])),
          "r"(__float_as_uint(b0)), "r"(__float_as_uint(b1)));
}

// ---------------- dtype detection + counting sort ----------------
__global__ void set_flag_kernel() { g_is64 = 1; }
__global__ void detect_kernel(const long long* __restrict__ ei) {
    int idx = blockIdx.x * blockDim.x + threadIdx.x;
    bool bad = false;
    for (int i = idx; i < E_EDGES; i += gridDim.x * blockDim.x) {
        long long v = ei[i];
        if (v < 0 || v >= N_NODES) bad = true;
    }
    if (__syncthreads_or(bad)) { if (threadIdx.x == 0) g_is64 = 0; }
}
__device__ __forceinline__ void get_edge(const void* ei, int e, int& s, int& d) {
    if (g_is64) {
        const long long* p = (const long long*)ei;
        s = (int)p[e]; d = (int)p[E_EDGES + e];
    } else {
        const int* p = (const int*)ei;
        s = p[e]; d = p[E_EDGES + e];
    }
}
__global__ void zero_pos_kernel() {
    int i = blockIdx.x * blockDim.x + threadIdx.x;
    if (i < N_NODES) g_pos[i] = 0;
}
__global__ void count_kernel(const void* __restrict__ ei) {
    int e = blockIdx.x * blockDim.x + threadIdx.x;
    if (e >= E_EDGES) return;
    int s, d; get_edge(ei, e, s, d);
    atomicAdd(&g_pos[d], 1);
}
__global__ void __launch_bounds__(1024) scan_kernel() {
    const int T = 1024, C = 10;
    __shared__ int sA[T], sB[T];
    int t = threadIdx.x, base = t * C, local[C], sum = 0;
#pragma unroll
    for (int c = 0; c < C; c++) {
        int i = base + c;
        local[c] = (i < N_NODES) ? g_pos[i] : 0;
        sum += local[c];
    }
    sA[t] = sum; __syncthreads();
    int* cur = sA; int* nxt = sB;
    for (int off = 1; off < T; off <<= 1) {
        int v = cur[t];
        if (t >= off) v += cur[t - off];
        nxt[t] = v; __syncthreads();
        int* tmp = cur; cur = nxt; nxt = tmp;
    }
    int running = (t > 0) ? cur[t - 1] : 0;
#pragma unroll
    for (int c = 0; c < C; c++) {
        int i = base + c;
        if (i < N_NODES) g_pos[i] = running;
        running += local[c];
    }
}
__global__ void scatter_sort_kernel(const void* __restrict__ ei) {
    int e = blockIdx.x * blockDim.x + threadIdx.x;
    if (e >= E_EDGES) return;
    int s, d; get_edge(ei, e, s, d);
    int pos = atomicAdd(&g_pos[d], 1);
    g_perm[pos] = e; g_sortedSrc[pos] = s; g_sortedDst[pos] = d;
}

// ---------------- agg = (1+eps[l]) * h ----------------
__global__ void scale_init_kernel(const float4* __restrict__ h, const float* __restrict__ eps,
                                  int l, float4* __restrict__ agg, int n4) {
    int i = blockIdx.x * blockDim.x + threadIdx.x;
    if (i >= n4) return;
    float s = 1.0f + eps[l];
    float4 v = h[i];
    v.x *= s; v.y *= s; v.z *= s; v.w *= s;
    agg[i] = v;
}

// ---------------- 3xTF32 mma.sync GEMM (128x128 tile, 8 warps) ----------------
// C[128,128] = A[128,K] @ B[K,128slice] with B in native [K, 512] layout.
// mode 0 (node): A dense fp32 [M,K]; epilogue +bias (+relu) -> out
// mode 1 (edge): A rows gathered via g_perm (sorted by dst); epilogue:
//   v = relu(D + bias + h[src]); stage to SMEM; run-combine by sorted dst; atomicAdd.
#define PITCH  132
#define CPITCH 136
#define TILE_FLOATS (4 * 16 * PITCH)                 // AsHi,AsLo,BsHi,BsLo
#define SMEM_NODE   (TILE_FLOATS * 4)                // bytes
#define SMEM_EDGE   ((TILE_FLOATS + 128 * CPITCH) * 4)

__global__ void __launch_bounds__(256) mma_fused_kernel(
        const float* __restrict__ A, const float* __restrict__ B,
        const float* __restrict__ bias, const float* __restrict__ hbuf,
        float* __restrict__ out, int M, int K, int mode, int doRelu) {
    extern __shared__ float sm[];
    float* AsHi = sm;
    float* AsLo = AsHi + 16 * PITCH;
    float* BsHi = AsLo + 16 * PITCH;
    float* BsLo = BsHi + 16 * PITCH;
    float* Cs   = BsLo + 16 * PITCH;   // [128][136], edge mode only

    int tid  = threadIdx.x;
    int wid  = tid >> 5;
    int lane = tid & 31;
    int gid  = lane >> 2;
    int tig  = lane & 3;
    int wm   = wid >> 2;               // 0..1
    int wn   = wid & 3;                // 0..3
    int brow = blockIdx.y * 128;
    int bcol = blockIdx.x * 128;

    // A loader mapping: one row per 2 threads
    int aRow = tid >> 1;
    int aK   = (tid & 1) * 8;
    const float* Ap;
    bool aValid = true;
    if (mode == 1) {
        Ap = A + (size_t)g_perm[brow + aRow] * EDGE_DIM + aK;
    } else {
        int gr = brow + aRow;
        aValid = gr < M;
        Ap = A + (size_t)(aValid ? gr : 0) * K + aK;
    }
    // B loader mapping
    int bK = tid >> 4;                 // 0..15
    int bC = (tid & 15) * 8;           // 0..120
    const float* Bp = B + (size_t)bK * D_DIM + bcol + bC;

    float acc[4][4][4];
#pragma unroll
    for (int i = 0; i < 4; i++)
#pragma unroll
        for (int j = 0; j < 4; j++)
#pragma unroll
            for (int q = 0; q < 4; q++) acc[i][j][q] = 0.f;

    int NC = K >> 4;
    for (int c = 0; c < NC; c++) {
        int k0 = c * 16;
        // load + split A chunk [128 x 16]
        {
            float4 v0, v1;
            if (aValid) {
                v0 = *(const float4*)(Ap + k0);
                v1 = *(const float4*)(Ap + k0 + 4);
            } else {
                v0 = make_float4(0.f, 0.f, 0.f, 0.f); v1 = v0;
            }
            float vv[8] = {v0.x, v0.y, v0.z, v0.w, v1.x, v1.y, v1.z, v1.w};
#pragma unroll
            for (int j = 0; j < 8; j++) {
                float hi, lo; tf32_split(vv[j], hi, lo);
                AsHi[(aK + j) * PITCH + aRow] = hi;
                AsLo[(aK + j) * PITCH + aRow] = lo;
            }
        }
        // load + split B chunk [16 x 128]
        {
            const float* bp = Bp + (size_t)k0 * D_DIM;
            float4 v0 = *(const float4*)(bp);
            float4 v1 = *(const float4*)(bp + 4);
            float vv[8] = {v0.x, v0.y, v0.z, v0.w, v1.x, v1.y, v1.z, v1.w};
#pragma unroll
            for (int j = 0; j < 8; j++) {
                float hi, lo; tf32_split(vv[j], hi, lo);
                BsHi[bK * PITCH + bC + j] = hi;
                BsLo[bK * PITCH + bC + j] = lo;
            }
        }
        __syncthreads();
        // compute: 2 k-steps of 8
#pragma unroll
        for (int ks = 0; ks < 16; ks += 8) {
            int r0 = (ks + tig) * PITCH;
            int r1 = (ks + tig + 4) * PITCH;
            float ahi[4][4], alo[4][4];
#pragma unroll
            for (int mf = 0; mf < 4; mf++) {
                int m0 = wm * 64 + mf * 16 + gid;
                ahi[mf][0] = AsHi[r0 + m0]; ahi[mf][1] = AsHi[r0 + m0 + 8];
                ahi[mf][2] = AsHi[r1 + m0]; ahi[mf][3] = AsHi[r1 + m0 + 8];
                alo[mf][0] = AsLo[r0 + m0]; alo[mf][1] = AsLo[r0 + m0 + 8];
                alo[mf][2] = AsLo[r1 + m0]; alo[mf][3] = AsLo[r1 + m0 + 8];
            }
#pragma unroll
            for (int nf = 0; nf < 4; nf++) {
                int n0 = wn * 32 + nf * 8 + gid;
                float bh0 = BsHi[r0 + n0], bh1 = BsHi[r1 + n0];
                float bl0 = BsLo[r0 + n0], bl1 = BsLo[r1 + n0];
#pragma unroll
                for (int mf = 0; mf < 4; mf++) {
                    mma_tf32(acc[mf][nf], ahi[mf], bh0, bh1);
                    mma_tf32(acc[mf][nf], ahi[mf], bl0, bl1);
                    mma_tf32(acc[mf][nf], alo[mf], bh0, bh1);
                }
            }
        }
        __syncthreads();
    }

    if (mode == 0) {
        // direct store: row = brow + wm*64 + mf*16 + gid (+8), col = bcol + wn*32 + nf*8 + 2tig
#pragma unroll
        for (int mf = 0; mf < 4; mf++) {
            int r0 = brow + wm * 64 + mf * 16 + gid;
#pragma unroll
            for (int nf = 0; nf < 4; nf++) {
                int col = bcol + wn * 32 + nf * 8 + 2 * tig;
                float b0 = bias[col], b1 = bias[col + 1];
                float v0 = acc[mf][nf][0] + b0;
                float v1 = acc[mf][nf][1] + b1;
                float v2 = acc[mf][nf][2] + b0;
                float v3 = acc[mf][nf][3] + b1;
                if (doRelu) {
                    v0 = fmaxf(v0, 0.f); v1 = fmaxf(v1, 0.f);
                    v2 = fmaxf(v2, 0.f); v3 = fmaxf(v3, 0.f);
                }
                if (r0 < M)     *(float2*)(out + (size_t)r0 * D_DIM + col)       = make_float2(v0, v1);
                if (r0 + 8 < M) *(float2*)(out + (size_t)(r0 + 8) * D_DIM + col) = make_float2(v2, v3);
            }
        }
    } else {
        // stage fragments to SMEM
#pragma unroll
        for (int mf = 0; mf < 4; mf++) {
            int rl = wm * 64 + mf * 16 + gid;
#pragma unroll
            for (int nf = 0; nf < 4; nf++) {
                int cl = wn * 32 + nf * 8 + 2 * tig;
                *(float2*)&Cs[rl * CPITCH + cl]       = make_float2(acc[mf][nf][0], acc[mf][nf][1]);
                *(float2*)&Cs[(rl + 8) * CPITCH + cl] = make_float2(acc[mf][nf][2], acc[mf][nf][3]);
            }
        }
        __syncthreads();
        // run-combined scatter (8 consecutive sorted rows per thread)
        int trow = (tid / 16) * 8;
        int tcol = (tid % 16) * 8;
        int colg = bcol + tcol;
        float bv[8];
        *(float4*)&bv[0] = *(const float4*)(bias + colg);
        *(float4*)&bv[4] = *(const float4*)(bias + colg + 4);
        float run[8];
        int prevDst = -1;
#pragma unroll
        for (int i = 0; i < 8; i++) {
            int r = brow + trow + i;
            int s = g_sortedSrc[r];
            int d = g_sortedDst[r];
            const float4* hp = (const float4*)(hbuf + (size_t)s * D_DIM + colg);
            float4 h0 = hp[0], h1 = hp[1];
            const float* cr = &Cs[(trow + i) * CPITCH + tcol];
            float m[8];
            m[0] = fmaxf(cr[0] + bv[0] + h0.x, 0.f);
            m[1] = fmaxf(cr[1] + bv[1] + h0.y, 0.f);
            m[2] = fmaxf(cr[2] + bv[2] + h0.z, 0.f);
            m[3] = fmaxf(cr[3] + bv[3] + h0.w, 0.f);
            m[4] = fmaxf(cr[4] + bv[4] + h1.x, 0.f);
            m[5] = fmaxf(cr[5] + bv[5] + h1.y, 0.f);
            m[6] = fmaxf(cr[6] + bv[6] + h1.z, 0.f);
            m[7] = fmaxf(cr[7] + bv[7] + h1.w, 0.f);
            if (d != prevDst) {
                if (prevDst >= 0) {
                    float* ap = out + (size_t)prevDst * D_DIM + colg;
#pragma unroll
                    for (int j = 0; j < 8; j++)
                        if (run[j] != 0.f) atomicAdd(&ap[j], run[j]);
                }
#pragma unroll
                for (int j = 0; j < 8; j++) run[j] = m[j];
                prevDst = d;
            } else {
#pragma unroll
                for (int j = 0; j < 8; j++) run[j] += m[j];
            }
        }
        if (prevDst >= 0) {
            float* ap = out + (size_t)prevDst * D_DIM + colg;
#pragma unroll
            for (int j = 0; j < 8; j++)
                if (run[j] != 0.f) atomicAdd(&ap[j], run[j]);
        }
    }
}

// ---------------- LayerNorm ----------------
__global__ void __launch_bounds__(128) layernorm_kernel(const float* __restrict__ g,
                                                        const float* __restrict__ gamma,
                                                        const float* __restrict__ beta,
                                                        float* __restrict__ out) {
    int row = blockIdx.x, t = threadIdx.x;
    const float4* gp = (const float4*)(g + (size_t)row * D_DIM);
    float4 v = gp[t];
    float s  = v.x + v.y + v.z + v.w;
    float sq = v.x * v.x + v.y * v.y + v.z * v.z + v.w * v.w;
#pragma unroll
    for (int o = 16; o > 0; o >>= 1) {
        s  += __shfl_xor_sync(0xffffffffu, s, o);
        sq += __shfl_xor_sync(0xffffffffu, sq, o);
    }
    __shared__ float red[8];
    int w = t >> 5;
    if ((t & 31) == 0) { red[w] = s; red[4 + w] = sq; }
    __syncthreads();
    s  = red[0] + red[1] + red[2] + red[3];
    sq = red[4] + red[5] + red[6] + red[7];
    float mu  = s * (1.0f / D_DIM);
    float var = sq * (1.0f / D_DIM) - mu * mu;
    float inv = rsqrtf(var + LN_EPS);
    float4 ga = *(const float4*)(gamma + t * 4);
    float4 be = *(const float4*)(beta + t * 4);
    float4 o;
    o.x = (v.x - mu) * inv * ga.x + be.x;
    o.y = (v.y - mu) * inv * ga.y + be.y;
    o.z = (v.z - mu) * inv * ga.z + be.z;
    o.w = (v.w - mu) * inv * ga.w + be.w;
    ((float4*)(out + (size_t)row * D_DIM))[t] = o;
}

// ---------------- launch ----------------
extern "C" void kernel_launch(void* const* d_in, const int* in_sizes, int n_in,
                              void* d_out, int out_size) {
    const float* x     = (const float*)d_in[0];
    const void*  ei    = d_in[1];
    const float* ea    = (const float*)d_in[2];
    const float* We    = (const float*)d_in[3];
    const float* be    = (const float*)d_in[4];
    const float* eps   = (const float*)d_in[5];
    const float* W1    = (const float*)d_in[6];
    const float* b1    = (const float*)d_in[7];
    const float* W2    = (const float*)d_in[8];
    const float* b2    = (const float*)d_in[9];
    const float* gamma = (const float*)d_in[10];
    const float* beta  = (const float*)d_in[11];
    const float* Wf    = (const float*)d_in[12];
    const float* bf    = (const float*)d_in[13];
    float* out = (float*)d_out;

    float *agg, *h, *t, *gg;
    cudaGetSymbolAddress((void**)&agg, g_agg);
    cudaGetSymbolAddress((void**)&h,   g_h);
    cudaGetSymbolAddress((void**)&t,   g_t);
    cudaGetSymbolAddress((void**)&gg,  g_g);

    cudaFuncSetAttribute(mma_fused_kernel, cudaFuncAttributeMaxDynamicSharedMemorySize, SMEM_EDGE);

    // ---- preprocessing: dtype detect + counting sort by dst ----
    set_flag_kernel<<<1, 1>>>();
    detect_kernel<<<64, 256>>>((const long long*)ei);
    zero_pos_kernel<<<(N_NODES + 255) / 256, 256>>>();
    count_kernel<<<(E_EDGES + 255) / 256, 256>>>(ei);
    scan_kernel<<<1, 1024>>>();
    scatter_sort_kernel<<<(E_EDGES + 255) / 256, 256>>>(ei);

    const int n4 = N_NODES * D_DIM / 4;
    dim3 gEdge(D_DIM / 128, E_EDGES / 128);           // (4, 1250)
    dim3 gNode(D_DIM / 128, (N_NODES + 127) / 128);   // (4, 79)

    for (int l = 0; l < L_LAYERS; l++) {
        const float* hCur = (l == 0) ? x : h;
        scale_init_kernel<<<(n4 + 255) / 256, 256>>>((const float4*)hCur, eps, l, (float4*)agg, n4);
        // agg[dst] += relu(EA@We + be + h[src])
        mma_fused_kernel<<<gEdge, 256, SMEM_EDGE>>>(
            ea, We + (size_t)l * EDGE_DIM * D_DIM, be + (size_t)l * D_DIM,
            hCur, agg, E_EDGES, EDGE_DIM, 1, 0);
        // t = relu(agg @ W1 + b1)
        mma_fused_kernel<<<gNode, 256, SMEM_NODE>>>(
            agg, W1 + (size_t)l * D_DIM * D_DIM, b1 + (size_t)l * D_DIM,
            nullptr, t, N_NODES, D_DIM, 0, 1);
        // gg = relu(t @ W2 + b2)
        mma_fused_kernel<<<gNode, 256, SMEM_NODE>>>(
            t, W2 + (size_t)l * D_DIM * D_DIM, b2 + (size_t)l * D_DIM,
            nullptr, gg, N_NODES, D_DIM, 0, 1);
        layernorm_kernel<<<N_NODES, 128>>>(gg, gamma + (size_t)l * D_DIM,
                                           beta + (size_t)l * D_DIM, h);
    }
    mma_fused_kernel<<<gNode, 256, SMEM_NODE>>>(h, Wf, bf, nullptr, out, N_NODES, D_DIM, 0, 0);
}

// round 6
// speedup vs baseline: 2.2786x; 1.7438x over previous
#include <cuda_runtime.h>
#include <cuda_bf16.h>
#include <cstdint>

#define N_NODES   10000
#define E_EDGES   160000
#define D_DIM     512
#define EDGE_DIM  128
#define L_LAYERS  3
#define LN_EPS    1e-5f

// ---------------- scratch ----------------
__device__ __align__(16) float g_agg[(size_t)N_NODES * D_DIM];
__device__ __align__(16) float g_h  [(size_t)N_NODES * D_DIM];
__device__ __align__(16) float g_t  [(size_t)N_NODES * D_DIM];
__device__ __align__(16) float g_g  [(size_t)N_NODES * D_DIM];
__device__ __align__(16) __nv_bfloat16 g_EAhi[(size_t)E_EDGES * EDGE_DIM];
__device__ __align__(16) __nv_bfloat16 g_EAlo[(size_t)E_EDGES * EDGE_DIM];
__device__ __align__(16) __nv_bfloat16 g_Wehi[(size_t)L_LAYERS * EDGE_DIM * D_DIM];
__device__ __align__(16) __nv_bfloat16 g_Welo[(size_t)L_LAYERS * EDGE_DIM * D_DIM];
__device__ __align__(16) __nv_bfloat16 g_W1hi[(size_t)L_LAYERS * D_DIM * D_DIM];
__device__ __align__(16) __nv_bfloat16 g_W1lo[(size_t)L_LAYERS * D_DIM * D_DIM];
__device__ __align__(16) __nv_bfloat16 g_W2hi[(size_t)L_LAYERS * D_DIM * D_DIM];
__device__ __align__(16) __nv_bfloat16 g_W2lo[(size_t)L_LAYERS * D_DIM * D_DIM];
__device__ __align__(16) __nv_bfloat16 g_Wfhi[(size_t)D_DIM * D_DIM];
__device__ __align__(16) __nv_bfloat16 g_Wflo[(size_t)D_DIM * D_DIM];
__device__ int g_pos[N_NODES];
__device__ int g_perm[E_EDGES];
__device__ int g_sortedSrc[E_EDGES];
__device__ int g_sortedDst[E_EDGES];
__device__ int g_is64;

// ---------------- helpers ----------------
__device__ __forceinline__ uint32_t smem_u32(const void* p) {
    uint32_t a;
    asm("{ .reg .u64 t; cvta.to.shared.u64 t, %1; cvt.u32.u64 %0, t; }" : "=r"(a) : "l"(p));
    return a;
}
__device__ __forceinline__ uint32_t pack_bf(float a, float b) {
    uint32_t lo16 = __bfloat16_as_ushort(__float2bfloat16_rn(a));
    uint32_t hi16 = __bfloat16_as_ushort(__float2bfloat16_rn(b));
    return lo16 | (hi16 << 16);
}
__device__ __forceinline__ void ldmx4(uint32_t* r, uint32_t addr) {
    asm volatile("ldmatrix.sync.aligned.m8n8.x4.shared.b16 {%0,%1,%2,%3}, [%4];"
        : "=r"(r[0]), "=r"(r[1]), "=r"(r[2]), "=r"(r[3]) : "r"(addr));
}
__device__ __forceinline__ void ldmx4t(uint32_t* r, uint32_t addr) {
    asm volatile("ldmatrix.sync.aligned.m8n8.x4.trans.shared.b16 {%0,%1,%2,%3}, [%4];"
        : "=r"(r[0]), "=r"(r[1]), "=r"(r[2]), "=r"(r[3]) : "r"(addr));
}
__device__ __forceinline__ void mma_bf16(float* c, const uint32_t* a, uint32_t b0, uint32_t b1) {
    asm volatile("mma.sync.aligned.m16n8k16.row.col.f32.bf16.bf16.f32 "
        "{%0,%1,%2,%3}, {%4,%5,%6,%7}, {%8,%9}, {%0,%1,%2,%3};"
        : "+f"(c[0]), "+f"(c[1]), "+f"(c[2]), "+f"(c[3])
        : "r"(a[0]), "r"(a[1]), "r"(a[2]), "r"(a[3]), "r"(b0), "r"(b1));
}

// ---------------- dtype detection + counting sort ----------------
__global__ void set_flag_kernel() { g_is64 = 1; }
__global__ void detect_kernel(const long long* __restrict__ ei) {
    int idx = blockIdx.x * blockDim.x + threadIdx.x;
    bool bad = false;
    for (int i = idx; i < E_EDGES; i += gridDim.x * blockDim.x) {
        long long v = ei[i];
        if (v < 0 || v >= N_NODES) bad = true;
    }
    if (__syncthreads_or(bad)) { if (threadIdx.x == 0) g_is64 = 0; }
}
__device__ __forceinline__ void get_edge(const void* ei, int e, int& s, int& d) {
    if (g_is64) {
        const long long* p = (const long long*)ei;
        s = (int)p[e]; d = (int)p[E_EDGES + e];
    } else {
        const int* p = (const int*)ei;
        s = p[e]; d = p[E_EDGES + e];
    }
}
__global__ void zero_pos_kernel() {
    int i = blockIdx.x * blockDim.x + threadIdx.x;
    if (i < N_NODES) g_pos[i] = 0;
}
__global__ void count_kernel(const void* __restrict__ ei) {
    int e = blockIdx.x * blockDim.x + threadIdx.x;
    if (e >= E_EDGES) return;
    int s, d; get_edge(ei, e, s, d);
    atomicAdd(&g_pos[d], 1);
}
__global__ void __launch_bounds__(1024) scan_kernel() {
    const int T = 1024, C = 10;
    __shared__ int sA[T], sB[T];
    int t = threadIdx.x, base = t * C, local[C], sum = 0;
#pragma unroll
    for (int c = 0; c < C; c++) {
        int i = base + c;
        local[c] = (i < N_NODES) ? g_pos[i] : 0;
        sum += local[c];
    }
    sA[t] = sum; __syncthreads();
    int* cur = sA; int* nxt = sB;
    for (int off = 1; off < T; off <<= 1) {
        int v = cur[t];
        if (t >= off) v += cur[t - off];
        nxt[t] = v; __syncthreads();
        int* tmp = cur; cur = nxt; nxt = tmp;
    }
    int running = (t > 0) ? cur[t - 1] : 0;
#pragma unroll
    for (int c = 0; c < C; c++) {
        int i = base + c;
        if (i < N_NODES) g_pos[i] = running;
        running += local[c];
    }
}
__global__ void scatter_sort_kernel(const void* __restrict__ ei) {
    int e = blockIdx.x * blockDim.x + threadIdx.x;
    if (e >= E_EDGES) return;
    int s, d; get_edge(ei, e, s, d);
    int pos = atomicAdd(&g_pos[d], 1);
    g_perm[pos] = e; g_sortedSrc[pos] = s; g_sortedDst[pos] = d;
}

// ---------------- pre-split kernels ----------------
__global__ void presplit_edges_kernel(const float* __restrict__ ea) {
    int idx = blockIdx.x * blockDim.x + threadIdx.x;   // E*32 threads, 4 elems each
    if (idx >= E_EDGES * (EDGE_DIM / 4)) return;
    int p = idx >> 5;
    int c4 = (idx & 31) * 4;
    int e = g_perm[p];
    float4 v = *(const float4*)(ea + (size_t)e * EDGE_DIM + c4);
    float h0 = __bfloat162float(__float2bfloat16_rn(v.x));
    float h1 = __bfloat162float(__float2bfloat16_rn(v.y));
    float h2 = __bfloat162float(__float2bfloat16_rn(v.z));
    float h3 = __bfloat162float(__float2bfloat16_rn(v.w));
    uint2 ph, pl;
    ph.x = pack_bf(v.x, v.y); ph.y = pack_bf(v.z, v.w);
    pl.x = pack_bf(v.x - h0, v.y - h1); pl.y = pack_bf(v.z - h2, v.w - h3);
    *(uint2*)(g_EAhi + (size_t)p * EDGE_DIM + c4) = ph;
    *(uint2*)(g_EAlo + (size_t)p * EDGE_DIM + c4) = pl;
}
__global__ void presplit_w_kernel(const float* __restrict__ src, __nv_bfloat16* __restrict__ hi,
                                  __nv_bfloat16* __restrict__ lo, int n4) {
    int i = blockIdx.x * blockDim.x + threadIdx.x;
    if (i >= n4) return;
    float4 v = ((const float4*)src)[i];
    float h0 = __bfloat162float(__float2bfloat16_rn(v.x));
    float h1 = __bfloat162float(__float2bfloat16_rn(v.y));
    float h2 = __bfloat162float(__float2bfloat16_rn(v.z));
    float h3 = __bfloat162float(__float2bfloat16_rn(v.w));
    uint2 ph, pl;
    ph.x = pack_bf(v.x, v.y); ph.y = pack_bf(v.z, v.w);
    pl.x = pack_bf(v.x - h0, v.y - h1); pl.y = pack_bf(v.z - h2, v.w - h3);
    ((uint2*)hi)[i] = ph;
    ((uint2*)lo)[i] = pl;
}

// ---------------- agg = (1+eps[l]) * h ----------------
__global__ void scale_init_kernel(const float4* __restrict__ h, const float* __restrict__ eps,
                                  int l, float4* __restrict__ agg, int n4) {
    int i = blockIdx.x * blockDim.x + threadIdx.x;
    if (i >= n4) return;
    float s = 1.0f + eps[l];
    float4 v = h[i];
    v.x *= s; v.y *= s; v.z *= s; v.w *= s;
    agg[i] = v;
}

// ---------------- bf16x3 ldmatrix GEMM (128x128 tile, 8 warps) ----------------
#define APITCH 40      // bf16 elems; 80B row stride
#define BPITCH 136     // 272B row stride
#define OFF_AHI 0
#define OFF_ALO (128 * APITCH * 2)              // 10240
#define OFF_BHI (2 * 128 * APITCH * 2)          // 20480
#define OFF_BLO (OFF_BHI + 32 * BPITCH * 2)     // 29184
#define SMEM_MAIN (OFF_BLO + 32 * BPITCH * 2)   // 37888
#define CPITCH 136
#define SMEM_EDGE (128 * CPITCH * 4)            // 69632 (Cs overlays mainloop bufs)

__global__ void __launch_bounds__(256, 2) mma_fused_kernel(
        const float* __restrict__ A,
        const __nv_bfloat16* __restrict__ Bhi, const __nv_bfloat16* __restrict__ Blo,
        const float* __restrict__ bias, const float* __restrict__ hbuf,
        float* __restrict__ out, int M, int K, int mode, int doRelu) {
    extern __shared__ char smc[];
    uint32_t sb = smem_u32(smc);
    float* Cs = (float*)smc;   // overlay (edge mode, used after mainloop)

    int tid  = threadIdx.x;
    int wid  = tid >> 5;
    int lane = tid & 31;
    int gid  = lane >> 2;
    int tig  = lane & 3;
    int wm   = wid >> 2;
    int wn   = wid & 3;
    int brow = blockIdx.y * 128;
    int bcol = blockIdx.x * 128;

    float acc[4][4][4];
#pragma unroll
    for (int i = 0; i < 4; i++)
#pragma unroll
        for (int j = 0; j < 4; j++)
#pragma unroll
            for (int q = 0; q < 4; q++) acc[i][j][q] = 0.f;

    // loader mappings
    int aRow = tid >> 1, aSeg = tid & 1;              // A: 2 threads/row, 16 elems each
    int bKr  = tid >> 3, bSeg = tid & 7;              // B: 8 threads/k-row, 16 elems each
    const float* ApF = nullptr;
    const __nv_bfloat16 *ApHi = nullptr, *ApLo = nullptr;
    if (mode == 1) {
        ApHi = g_EAhi + (size_t)(brow + aRow) * EDGE_DIM + aSeg * 16;
        ApLo = g_EAlo + (size_t)(brow + aRow) * EDGE_DIM + aSeg * 16;
    } else {
        int gr = brow + aRow;
        ApF = A + (size_t)(gr < M ? gr : 0) * K + aSeg * 16;
    }
    const __nv_bfloat16* BpHi = Bhi + (size_t)bKr * D_DIM + bcol + bSeg * 16;
    const __nv_bfloat16* BpLo = Blo + (size_t)bKr * D_DIM + bcol + bSeg * 16;
    uint32_t aSt = sb + OFF_AHI + (uint32_t)(aRow * APITCH + aSeg * 16) * 2;
    uint32_t bSt = sb + OFF_BHI + (uint32_t)(bKr * BPITCH + bSeg * 16) * 2;

    int NC = K >> 5;
    for (int c = 0; c < NC; c++) {
        int k0 = c * 32;
        // ---- load A chunk (16 elems/thread: two int4 each for hi/lo) ----
        if (mode == 1) {
            int4 h0 = *(const int4*)(ApHi + k0);
            int4 l0 = *(const int4*)(ApLo + k0);
            int4 h1 = *(const int4*)(ApHi + k0 + 8);
            int4 l1 = *(const int4*)(ApLo + k0 + 8);
            *(int4*)(smc + (aSt - sb))      = h0;
            *(int4*)(smc + (aSt - sb) + 16) = h1;
            *(int4*)(smc + (aSt - sb) + OFF_ALO)      = l0;
            *(int4*)(smc + (aSt - sb) + OFF_ALO + 16) = l1;
        } else {
            float4 v0 = *(const float4*)(ApF + k0);
            float4 v1 = *(const float4*)(ApF + k0 + 4);
            float4 v2 = *(const float4*)(ApF + k0 + 8);
            float4 v3 = *(const float4*)(ApF + k0 + 12);
            float vv[16] = {v0.x, v0.y, v0.z, v0.w, v1.x, v1.y, v1.z, v1.w,
                            v2.x, v2.y, v2.z, v2.w, v3.x, v3.y, v3.z, v3.w};
            uint32_t ph[8], pl[8];
#pragma unroll
            for (int j = 0; j < 8; j++) {
                float f0 = vv[2 * j], f1 = vv[2 * j + 1];
                float h0 = __bfloat162float(__float2bfloat16_rn(f0));
                float h1 = __bfloat162float(__float2bfloat16_rn(f1));
                ph[j] = pack_bf(f0, f1);
                pl[j] = pack_bf(f0 - h0, f1 - h1);
            }
            *(int4*)(smc + (aSt - sb))      = *(int4*)&ph[0];
            *(int4*)(smc + (aSt - sb) + 16) = *(int4*)&ph[4];
            *(int4*)(smc + (aSt - sb) + OFF_ALO)      = *(int4*)&pl[0];
            *(int4*)(smc + (aSt - sb) + OFF_ALO + 16) = *(int4*)&pl[4];
        }
        // ---- load B chunk (FIX: full 16 elems/thread = two int4 for hi and lo) ----
        {
            const __nv_bfloat16* bp = BpHi + (size_t)k0 * D_DIM;
            const __nv_bfloat16* bq = BpLo + (size_t)k0 * D_DIM;
            int4 h0 = *(const int4*)(bp);
            int4 h1 = *(const int4*)(bp + 8);
            int4 l0 = *(const int4*)(bq);
            int4 l1 = *(const int4*)(bq + 8);
            char* dst = smc + (bSt - sb);
            *(int4*)(dst)      = h0;
            *(int4*)(dst + 16) = h1;
            *(int4*)(dst + (OFF_BLO - OFF_BHI))      = l0;
            *(int4*)(dst + (OFF_BLO - OFF_BHI) + 16) = l1;
        }
        __syncthreads();
        // ---- compute 2 k16 steps ----
#pragma unroll
        for (int ks = 0; ks < 32; ks += 16) {
            uint32_t bh[2][4], bl[2][4];
            int bkrow = ks + ((lane >> 3) & 1) * 8 + (lane & 7);
            int bnc   = (lane >> 4) * 8;
#pragma unroll
            for (int pn = 0; pn < 2; pn++) {
                uint32_t bd = sb + OFF_BHI + (uint32_t)(bkrow * BPITCH + wn * 32 + pn * 16 + bnc) * 2;
                ldmx4t(bh[pn], bd);
                ldmx4t(bl[pn], bd + (OFF_BLO - OFF_BHI));
            }
            int arow = ((lane >> 3) & 1) * 8 + (lane & 7);
            int akc  = ks + (lane >> 4) * 8;
#pragma unroll
            for (int mf = 0; mf < 4; mf++) {
                uint32_t ad = sb + OFF_AHI + (uint32_t)((wm * 64 + mf * 16 + arow) * APITCH + akc) * 2;
                uint32_t ah[4], al[4];
                ldmx4(ah, ad);
                ldmx4(al, ad + OFF_ALO);
#pragma unroll
                for (int nf = 0; nf < 4; nf++) {
                    int pn = nf >> 1, sub = nf & 1;
                    mma_bf16(acc[mf][nf], ah, bh[pn][sub * 2], bh[pn][sub * 2 + 1]);
                    mma_bf16(acc[mf][nf], ah, bl[pn][sub * 2], bl[pn][sub * 2 + 1]);
                    mma_bf16(acc[mf][nf], al, bh[pn][sub * 2], bh[pn][sub * 2 + 1]);
                }
            }
        }
        __syncthreads();
    }

    if (mode == 0) {
#pragma unroll
        for (int mf = 0; mf < 4; mf++) {
            int r0 = brow + wm * 64 + mf * 16 + gid;
#pragma unroll
            for (int nf = 0; nf < 4; nf++) {
                int col = bcol + wn * 32 + nf * 8 + 2 * tig;
                float b0 = bias[col], b1 = bias[col + 1];
                float v0 = acc[mf][nf][0] + b0;
                float v1 = acc[mf][nf][1] + b1;
                float v2 = acc[mf][nf][2] + b0;
                float v3 = acc[mf][nf][3] + b1;
                if (doRelu) {
                    v0 = fmaxf(v0, 0.f); v1 = fmaxf(v1, 0.f);
                    v2 = fmaxf(v2, 0.f); v3 = fmaxf(v3, 0.f);
                }
                if (r0 < M)     *(float2*)(out + (size_t)r0 * D_DIM + col)       = make_float2(v0, v1);
                if (r0 + 8 < M) *(float2*)(out + (size_t)(r0 + 8) * D_DIM + col) = make_float2(v2, v3);
            }
        }
    } else {
        // stage fragments to SMEM (overlay)
#pragma unroll
        for (int mf = 0; mf < 4; mf++) {
            int rl = wm * 64 + mf * 16 + gid;
#pragma unroll
            for (int nf = 0; nf < 4; nf++) {
                int cl = wn * 32 + nf * 8 + 2 * tig;
                *(float2*)&Cs[rl * CPITCH + cl]       = make_float2(acc[mf][nf][0], acc[mf][nf][1]);
                *(float2*)&Cs[(rl + 8) * CPITCH + cl] = make_float2(acc[mf][nf][2], acc[mf][nf][3]);
            }
        }
        __syncthreads();
        // run-combined scatter: 8 consecutive sorted rows per thread
        int trow = (tid / 16) * 8;
        int tcol = (tid % 16) * 8;
        int colg = bcol + tcol;
        float bv[8];
        *(float4*)&bv[0] = *(const float4*)(bias + colg);
        *(float4*)&bv[4] = *(const float4*)(bias + colg + 4);
        float run[8];
        int prevDst = -1;
#pragma unroll
        for (int i = 0; i < 8; i++) {
            int r = brow + trow + i;
            int s = g_sortedSrc[r];
            int d = g_sortedDst[r];
            const float4* hp = (const float4*)(hbuf + (size_t)s * D_DIM + colg);
            float4 h0 = hp[0], h1 = hp[1];
            const float* cr = &Cs[(trow + i) * CPITCH + tcol];
            float m[8];
            m[0] = fmaxf(cr[0] + bv[0] + h0.x, 0.f);
            m[1] = fmaxf(cr[1] + bv[1] + h0.y, 0.f);
            m[2] = fmaxf(cr[2] + bv[2] + h0.z, 0.f);
            m[3] = fmaxf(cr[3] + bv[3] + h0.w, 0.f);
            m[4] = fmaxf(cr[4] + bv[4] + h1.x, 0.f);
            m[5] = fmaxf(cr[5] + bv[5] + h1.y, 0.f);
            m[6] = fmaxf(cr[6] + bv[6] + h1.z, 0.f);
            m[7] = fmaxf(cr[7] + bv[7] + h1.w, 0.f);
            if (d != prevDst) {
                if (prevDst >= 0) {
                    float* ap = out + (size_t)prevDst * D_DIM + colg;
#pragma unroll
                    for (int j = 0; j < 8; j++)
                        if (run[j] != 0.f) atomicAdd(&ap[j], run[j]);
                }
#pragma unroll
                for (int j = 0; j < 8; j++) run[j] = m[j];
                prevDst = d;
            } else {
#pragma unroll
                for (int j = 0; j < 8; j++) run[j] += m[j];
            }
        }
        if (prevDst >= 0) {
            float* ap = out + (size_t)prevDst * D_DIM + colg;
#pragma unroll
            for (int j = 0; j < 8; j++)
                if (run[j] != 0.f) atomicAdd(&ap[j], run[j]);
        }
    }
}

// ---------------- LayerNorm ----------------
__global__ void __launch_bounds__(128) layernorm_kernel(const float* __restrict__ g,
                                                        const float* __restrict__ gamma,
                                                        const float* __restrict__ beta,
                                                        float* __restrict__ out) {
    int row = blockIdx.x, t = threadIdx.x;
    const float4* gp = (const float4*)(g + (size_t)row * D_DIM);
    float4 v = gp[t];
    float s  = v.x + v.y + v.z + v.w;
    float sq = v.x * v.x + v.y * v.y + v.z * v.z + v.w * v.w;
#pragma unroll
    for (int o = 16; o > 0; o >>= 1) {
        s  += __shfl_xor_sync(0xffffffffu, s, o);
        sq += __shfl_xor_sync(0xffffffffu, sq, o);
    }
    __shared__ float red[8];
    int w = t >> 5;
    if ((t & 31) == 0) { red[w] = s; red[4 + w] = sq; }
    __syncthreads();
    s  = red[0] + red[1] + red[2] + red[3];
    sq = red[4] + red[5] + red[6] + red[7];
    float mu  = s * (1.0f / D_DIM);
    float var = sq * (1.0f / D_DIM) - mu * mu;
    float inv = rsqrtf(var + LN_EPS);
    float4 ga = *(const float4*)(gamma + t * 4);
    float4 be = *(const float4*)(beta + t * 4);
    float4 o;
    o.x = (v.x - mu) * inv * ga.x + be.x;
    o.y = (v.y - mu) * inv * ga.y + be.y;
    o.z = (v.z - mu) * inv * ga.z + be.z;
    o.w = (v.w - mu) * inv * ga.w + be.w;
    ((float4*)(out + (size_t)row * D_DIM))[t] = o;
}

// ---------------- launch ----------------
extern "C" void kernel_launch(void* const* d_in, const int* in_sizes, int n_in,
                              void* d_out, int out_size) {
    const float* x     = (const float*)d_in[0];
    const void*  ei    = d_in[1];
    const float* ea    = (const float*)d_in[2];
    const float* We    = (const float*)d_in[3];
    const float* be    = (const float*)d_in[4];
    const float* eps   = (const float*)d_in[5];
    const float* W1    = (const float*)d_in[6];
    const float* b1    = (const float*)d_in[7];
    const float* W2    = (const float*)d_in[8];
    const float* b2    = (const float*)d_in[9];
    const float* gamma = (const float*)d_in[10];
    const float* beta  = (const float*)d_in[11];
    const float* Wf    = (const float*)d_in[12];
    const float* bf    = (const float*)d_in[13];
    float* out = (float*)d_out;

    float *agg, *h, *t, *gg;
    __nv_bfloat16 *Wehi, *Welo, *W1hi, *W1lo, *W2hi, *W2lo, *Wfhi, *Wflo;
    cudaGetSymbolAddress((void**)&agg, g_agg);
    cudaGetSymbolAddress((void**)&h,   g_h);
    cudaGetSymbolAddress((void**)&t,   g_t);
    cudaGetSymbolAddress((void**)&gg,  g_g);
    cudaGetSymbolAddress((void**)&Wehi, g_Wehi);
    cudaGetSymbolAddress((void**)&Welo, g_Welo);
    cudaGetSymbolAddress((void**)&W1hi, g_W1hi);
    cudaGetSymbolAddress((void**)&W1lo, g_W1lo);
    cudaGetSymbolAddress((void**)&W2hi, g_W2hi);
    cudaGetSymbolAddress((void**)&W2lo, g_W2lo);
    cudaGetSymbolAddress((void**)&Wfhi, g_Wfhi);
    cudaGetSymbolAddress((void**)&Wflo, g_Wflo);

    cudaFuncSetAttribute(mma_fused_kernel, cudaFuncAttributeMaxDynamicSharedMemorySize, SMEM_EDGE);

    // ---- preprocessing ----
    set_flag_kernel<<<1, 1>>>();
    detect_kernel<<<64, 256>>>((const long long*)ei);
    zero_pos_kernel<<<(N_NODES + 255) / 256, 256>>>();
    count_kernel<<<(E_EDGES + 255) / 256, 256>>>(ei);
    scan_kernel<<<1, 1024>>>();
    scatter_sort_kernel<<<(E_EDGES + 255) / 256, 256>>>(ei);

    int nthr = E_EDGES * (EDGE_DIM / 4);
    presplit_edges_kernel<<<(nthr + 255) / 256, 256>>>(ea);
    int we4 = L_LAYERS * EDGE_DIM * D_DIM / 4;
    int w4  = L_LAYERS * D_DIM * D_DIM / 4;
    int wf4 = D_DIM * D_DIM / 4;
    presplit_w_kernel<<<(we4 + 255) / 256, 256>>>(We, Wehi, Welo, we4);
    presplit_w_kernel<<<(w4 + 255) / 256, 256>>>(W1, W1hi, W1lo, w4);
    presplit_w_kernel<<<(w4 + 255) / 256, 256>>>(W2, W2hi, W2lo, w4);
    presplit_w_kernel<<<(wf4 + 255) / 256, 256>>>(Wf, Wfhi, Wflo, wf4);

    const int n4 = N_NODES * D_DIM / 4;
    dim3 gEdge(D_DIM / 128, E_EDGES / 128);           // (4, 1250)
    dim3 gNode(D_DIM / 128, (N_NODES + 127) / 128);   // (4, 79)
    const size_t WSTEP = (size_t)D_DIM * D_DIM;

    for (int l = 0; l < L_LAYERS; l++) {
        const float* hCur = (l == 0) ? x : h;
        scale_init_kernel<<<(n4 + 255) / 256, 256>>>((const float4*)hCur, eps, l, (float4*)agg, n4);
        mma_fused_kernel<<<gEdge, 256, SMEM_EDGE>>>(
            nullptr, Wehi + (size_t)l * EDGE_DIM * D_DIM, Welo + (size_t)l * EDGE_DIM * D_DIM,
            be + (size_t)l * D_DIM, hCur, agg, E_EDGES, EDGE_DIM, 1, 0);
        mma_fused_kernel<<<gNode, 256, SMEM_MAIN>>>(
            agg, W1hi + l * WSTEP, W1lo + l * WSTEP, b1 + (size_t)l * D_DIM,
            nullptr, t, N_NODES, D_DIM, 0, 1);
        mma_fused_kernel<<<gNode, 256, SMEM_MAIN>>>(
            t, W2hi + l * WSTEP, W2lo + l * WSTEP, b2 + (size_t)l * D_DIM,
            nullptr, gg, N_NODES, D_DIM, 0, 1);
        layernorm_kernel<<<N_NODES, 128>>>(gg, gamma + (size_t)l * D_DIM,
                                           beta + (size_t)l * D_DIM, h);
    }
    mma_fused_kernel<<<gNode, 256, SMEM_MAIN>>>(h, Wfhi, Wflo, bf, nullptr, out,
                                                N_NODES, D_DIM, 0, 0);
}

// round 7
// speedup vs baseline: 2.7748x; 1.2177x over previous
#include <cuda_runtime.h>
#include <cuda_bf16.h>
#include <cstdint>

#define N_NODES   10000
#define E_EDGES   160000
#define D_DIM     512
#define EDGE_DIM  128
#define L_LAYERS  3
#define LN_EPS    1e-5f

// ---------------- scratch ----------------
__device__ __align__(16) float g_agg[(size_t)N_NODES * D_DIM];
__device__ __align__(16) float g_h  [(size_t)N_NODES * D_DIM];
__device__ __align__(16) float g_t  [(size_t)N_NODES * D_DIM];
__device__ __align__(16) float g_g  [(size_t)N_NODES * D_DIM];
__device__ __align__(16) __nv_bfloat16 g_EAhi[(size_t)E_EDGES * EDGE_DIM];
__device__ __align__(16) __nv_bfloat16 g_EAlo[(size_t)E_EDGES * EDGE_DIM];
__device__ __align__(16) __nv_bfloat16 g_Wehi[(size_t)L_LAYERS * EDGE_DIM * D_DIM];
__device__ __align__(16) __nv_bfloat16 g_Welo[(size_t)L_LAYERS * EDGE_DIM * D_DIM];
__device__ __align__(16) __nv_bfloat16 g_W1hi[(size_t)L_LAYERS * D_DIM * D_DIM];
__device__ __align__(16) __nv_bfloat16 g_W1lo[(size_t)L_LAYERS * D_DIM * D_DIM];
__device__ __align__(16) __nv_bfloat16 g_W2hi[(size_t)L_LAYERS * D_DIM * D_DIM];
__device__ __align__(16) __nv_bfloat16 g_W2lo[(size_t)L_LAYERS * D_DIM * D_DIM];
__device__ __align__(16) __nv_bfloat16 g_Wfhi[(size_t)D_DIM * D_DIM];
__device__ __align__(16) __nv_bfloat16 g_Wflo[(size_t)D_DIM * D_DIM];
__device__ int g_pos[N_NODES];
__device__ int g_perm[E_EDGES];
__device__ int g_sortedSrc[E_EDGES];
__device__ int g_sortedDst[E_EDGES];
__device__ int g_is64;

// ---------------- helpers ----------------
__device__ __forceinline__ uint32_t smem_u32(const void* p) {
    uint32_t a;
    asm("{ .reg .u64 t; cvta.to.shared.u64 t, %1; cvt.u32.u64 %0, t; }" : "=r"(a) : "l"(p));
    return a;
}
__device__ __forceinline__ uint32_t pack_bf(float a, float b) {
    uint32_t lo16 = __bfloat16_as_ushort(__float2bfloat16_rn(a));
    uint32_t hi16 = __bfloat16_as_ushort(__float2bfloat16_rn(b));
    return lo16 | (hi16 << 16);
}
__device__ __forceinline__ void ldmx4(uint32_t* r, uint32_t addr) {
    asm volatile("ldmatrix.sync.aligned.m8n8.x4.shared.b16 {%0,%1,%2,%3}, [%4];"
        : "=r"(r[0]), "=r"(r[1]), "=r"(r[2]), "=r"(r[3]) : "r"(addr));
}
__device__ __forceinline__ void ldmx4t(uint32_t* r, uint32_t addr) {
    asm volatile("ldmatrix.sync.aligned.m8n8.x4.trans.shared.b16 {%0,%1,%2,%3}, [%4];"
        : "=r"(r[0]), "=r"(r[1]), "=r"(r[2]), "=r"(r[3]) : "r"(addr));
}
__device__ __forceinline__ void mma_bf16(float* c, const uint32_t* a, uint32_t b0, uint32_t b1) {
    asm volatile("mma.sync.aligned.m16n8k16.row.col.f32.bf16.bf16.f32 "
        "{%0,%1,%2,%3}, {%4,%5,%6,%7}, {%8,%9}, {%0,%1,%2,%3};"
        : "+f"(c[0]), "+f"(c[1]), "+f"(c[2]), "+f"(c[3])
        : "r"(a[0]), "r"(a[1]), "r"(a[2]), "r"(a[3]), "r"(b0), "r"(b1));
}
__device__ __forceinline__ void cp16(uint32_t dst, const void* src) {
    asm volatile("cp.async.cg.shared.global [%0], [%1], 16;" :: "r"(dst), "l"(src));
}
__device__ __forceinline__ void cp_commit() {
    asm volatile("cp.async.commit_group;");
}
__device__ __forceinline__ void cp_wait0() {
    asm volatile("cp.async.wait_group 0;");
}

// ---------------- dtype detection + counting sort ----------------
__global__ void set_flag_kernel() { g_is64 = 1; }
__global__ void detect_kernel(const long long* __restrict__ ei) {
    int idx = blockIdx.x * blockDim.x + threadIdx.x;
    bool bad = false;
    for (int i = idx; i < E_EDGES; i += gridDim.x * blockDim.x) {
        long long v = ei[i];
        if (v < 0 || v >= N_NODES) bad = true;
    }
    if (__syncthreads_or(bad)) { if (threadIdx.x == 0) g_is64 = 0; }
}
__device__ __forceinline__ void get_edge(const void* ei, int e, int& s, int& d) {
    if (g_is64) {
        const long long* p = (const long long*)ei;
        s = (int)p[e]; d = (int)p[E_EDGES + e];
    } else {
        const int* p = (const int*)ei;
        s = p[e]; d = p[E_EDGES + e];
    }
}
__global__ void zero_pos_kernel() {
    int i = blockIdx.x * blockDim.x + threadIdx.x;
    if (i < N_NODES) g_pos[i] = 0;
}
__global__ void count_kernel(const void* __restrict__ ei) {
    int e = blockIdx.x * blockDim.x + threadIdx.x;
    if (e >= E_EDGES) return;
    int s, d; get_edge(ei, e, s, d);
    atomicAdd(&g_pos[d], 1);
}
__global__ void __launch_bounds__(1024) scan_kernel() {
    const int T = 1024, C = 10;
    __shared__ int sA[T], sB[T];
    int t = threadIdx.x, base = t * C, local[C], sum = 0;
#pragma unroll
    for (int c = 0; c < C; c++) {
        int i = base + c;
        local[c] = (i < N_NODES) ? g_pos[i] : 0;
        sum += local[c];
    }
    sA[t] = sum; __syncthreads();
    int* cur = sA; int* nxt = sB;
    for (int off = 1; off < T; off <<= 1) {
        int v = cur[t];
        if (t >= off) v += cur[t - off];
        nxt[t] = v; __syncthreads();
        int* tmp = cur; cur = nxt; nxt = tmp;
    }
    int running = (t > 0) ? cur[t - 1] : 0;
#pragma unroll
    for (int c = 0; c < C; c++) {
        int i = base + c;
        if (i < N_NODES) g_pos[i] = running;
        running += local[c];
    }
}
__global__ void scatter_sort_kernel(const void* __restrict__ ei) {
    int e = blockIdx.x * blockDim.x + threadIdx.x;
    if (e >= E_EDGES) return;
    int s, d; get_edge(ei, e, s, d);
    int pos = atomicAdd(&g_pos[d], 1);
    g_perm[pos] = e; g_sortedSrc[pos] = s; g_sortedDst[pos] = d;
}

// ---------------- pre-split kernels ----------------
__global__ void presplit_edges_kernel(const float* __restrict__ ea) {
    int idx = blockIdx.x * blockDim.x + threadIdx.x;
    if (idx >= E_EDGES * (EDGE_DIM / 4)) return;
    int p = idx >> 5;
    int c4 = (idx & 31) * 4;
    int e = g_perm[p];
    float4 v = *(const float4*)(ea + (size_t)e * EDGE_DIM + c4);
    float h0 = __bfloat162float(__float2bfloat16_rn(v.x));
    float h1 = __bfloat162float(__float2bfloat16_rn(v.y));
    float h2 = __bfloat162float(__float2bfloat16_rn(v.z));
    float h3 = __bfloat162float(__float2bfloat16_rn(v.w));
    uint2 ph, pl;
    ph.x = pack_bf(v.x, v.y); ph.y = pack_bf(v.z, v.w);
    pl.x = pack_bf(v.x - h0, v.y - h1); pl.y = pack_bf(v.z - h2, v.w - h3);
    *(uint2*)(g_EAhi + (size_t)p * EDGE_DIM + c4) = ph;
    *(uint2*)(g_EAlo + (size_t)p * EDGE_DIM + c4) = pl;
}
__global__ void presplit_w_kernel(const float* __restrict__ src, __nv_bfloat16* __restrict__ hi,
                                  __nv_bfloat16* __restrict__ lo, int n4) {
    int i = blockIdx.x * blockDim.x + threadIdx.x;
    if (i >= n4) return;
    float4 v = ((const float4*)src)[i];
    float h0 = __bfloat162float(__float2bfloat16_rn(v.x));
    float h1 = __bfloat162float(__float2bfloat16_rn(v.y));
    float h2 = __bfloat162float(__float2bfloat16_rn(v.z));
    float h3 = __bfloat162float(__float2bfloat16_rn(v.w));
    uint2 ph, pl;
    ph.x = pack_bf(v.x, v.y); ph.y = pack_bf(v.z, v.w);
    pl.x = pack_bf(v.x - h0, v.y - h1); pl.y = pack_bf(v.z - h2, v.w - h3);
    ((uint2*)hi)[i] = ph;
    ((uint2*)lo)[i] = pl;
}

// ---------------- agg = (1+eps[l]) * h ----------------
__global__ void scale_init_kernel(const float4* __restrict__ h, const float* __restrict__ eps,
                                  int l, float4* __restrict__ agg, int n4) {
    int i = blockIdx.x * blockDim.x + threadIdx.x;
    if (i >= n4) return;
    float s = 1.0f + eps[l];
    float4 v = h[i];
    v.x *= s; v.y *= s; v.z *= s; v.w *= s;
    agg[i] = v;
}

// ---------------- bf16x3 ldmatrix GEMM, cp.async double-buffered ----------------
#define APITCH 40      // bf16 elems; 80B row stride
#define BPITCH 136     // 272B row stride
#define ST_AHI 0
#define ST_ALO (128 * APITCH * 2)               // 10240
#define ST_BHI (2 * 128 * APITCH * 2)           // 20480
#define ST_BLO (ST_BHI + 32 * BPITCH * 2)       // 29184
#define STAGE_BYTES (ST_BLO + 32 * BPITCH * 2)  // 37888
#define SMEM_TOTAL (2 * STAGE_BYTES)            // 75776 (Cs overlay fits: 69632)
#define CPITCH 136

__global__ void __launch_bounds__(256, 2) mma_fused_kernel(
        const float* __restrict__ A,
        const __nv_bfloat16* __restrict__ Bhi, const __nv_bfloat16* __restrict__ Blo,
        const float* __restrict__ bias, const float* __restrict__ hbuf,
        float* __restrict__ out, int M, int K, int mode, int doRelu) {
    extern __shared__ char smc[];
    uint32_t sb = smem_u32(smc);
    float* Cs = (float*)smc;

    int tid  = threadIdx.x;
    int wid  = tid >> 5;
    int lane = tid & 31;
    int gid  = lane >> 2;
    int tig  = lane & 3;
    int wm   = wid >> 2;
    int wn   = wid & 3;
    int brow = blockIdx.y * 128;
    int bcol = blockIdx.x * 128;

    float acc[4][4][4];
#pragma unroll
    for (int i = 0; i < 4; i++)
#pragma unroll
        for (int j = 0; j < 4; j++)
#pragma unroll
            for (int q = 0; q < 4; q++) acc[i][j][q] = 0.f;

    // loader mappings
    int aRow = tid >> 1, aSeg = tid & 1;
    int bKr  = tid >> 3, bSeg = tid & 7;
    const float* ApF = nullptr;
    const __nv_bfloat16 *ApHi = nullptr, *ApLo = nullptr;
    if (mode == 1) {
        ApHi = g_EAhi + (size_t)(brow + aRow) * EDGE_DIM + aSeg * 16;
        ApLo = g_EAlo + (size_t)(brow + aRow) * EDGE_DIM + aSeg * 16;
    } else {
        int gr = brow + aRow;
        ApF = A + (size_t)(gr < M ? gr : 0) * K + aSeg * 16;
    }
    const __nv_bfloat16* BpHi = Bhi + (size_t)bKr * D_DIM + bcol + bSeg * 16;
    const __nv_bfloat16* BpLo = Blo + (size_t)bKr * D_DIM + bcol + bSeg * 16;
    uint32_t aRel = ST_AHI + (uint32_t)(aRow * APITCH + aSeg * 16) * 2;
    uint32_t bRel = ST_BHI + (uint32_t)(bKr * BPITCH + bSeg * 16) * 2;

    int NC = K >> 5;
    float4 stA[4];   // node-mode A staging registers

    // ---- prologue: fill stage 0 ----
    {
        if (mode == 1) {
            cp16(sb + aRel,                ApHi);
            cp16(sb + aRel + 16,           ApHi + 8);
            cp16(sb + aRel + ST_ALO,       ApLo);
            cp16(sb + aRel + ST_ALO + 16,  ApLo + 8);
        } else {
            stA[0] = *(const float4*)(ApF);
            stA[1] = *(const float4*)(ApF + 4);
            stA[2] = *(const float4*)(ApF + 8);
            stA[3] = *(const float4*)(ApF + 12);
        }
        cp16(sb + bRel,                              BpHi);
        cp16(sb + bRel + 16,                         BpHi + 8);
        cp16(sb + bRel + (ST_BLO - ST_BHI),          BpLo);
        cp16(sb + bRel + (ST_BLO - ST_BHI) + 16,     BpLo + 8);
        cp_commit();
        if (mode == 0) {
            const float* vv = (const float*)stA;
            uint32_t ph[8], pl[8];
#pragma unroll
            for (int j = 0; j < 8; j++) {
                float f0 = vv[2 * j], f1 = vv[2 * j + 1];
                float h0 = __bfloat162float(__float2bfloat16_rn(f0));
                float h1 = __bfloat162float(__float2bfloat16_rn(f1));
                ph[j] = pack_bf(f0, f1);
                pl[j] = pack_bf(f0 - h0, f1 - h1);
            }
            *(int4*)(smc + aRel)               = *(int4*)&ph[0];
            *(int4*)(smc + aRel + 16)          = *(int4*)&ph[4];
            *(int4*)(smc + aRel + ST_ALO)      = *(int4*)&pl[0];
            *(int4*)(smc + aRel + ST_ALO + 16) = *(int4*)&pl[4];
        }
    }

    for (int c = 0; c < NC; c++) {
        uint32_t so = (c & 1) ? STAGE_BYTES : 0;
        uint32_t no = so ^ STAGE_BYTES;
        cp_wait0();
        __syncthreads();
        // issue next chunk loads
        if (c + 1 < NC) {
            int k1 = (c + 1) * 32;
            if (mode == 1) {
                cp16(sb + no + aRel,               ApHi + k1);
                cp16(sb + no + aRel + 16,          ApHi + k1 + 8);
                cp16(sb + no + aRel + ST_ALO,      ApLo + k1);
                cp16(sb + no + aRel + ST_ALO + 16, ApLo + k1 + 8);
            } else {
                stA[0] = *(const float4*)(ApF + k1);
                stA[1] = *(const float4*)(ApF + k1 + 4);
                stA[2] = *(const float4*)(ApF + k1 + 8);
                stA[3] = *(const float4*)(ApF + k1 + 12);
            }
            const __nv_bfloat16* bp = BpHi + (size_t)(c + 1) * 32 * D_DIM;
            const __nv_bfloat16* bq = BpLo + (size_t)(c + 1) * 32 * D_DIM;
            cp16(sb + no + bRel,                          bp);
            cp16(sb + no + bRel + 16,                     bp + 8);
            cp16(sb + no + bRel + (ST_BLO - ST_BHI),      bq);
            cp16(sb + no + bRel + (ST_BLO - ST_BHI) + 16, bq + 8);
            cp_commit();
        }
        // ---- compute on stage so: 2 k16 steps ----
#pragma unroll
        for (int ks = 0; ks < 32; ks += 16) {
            uint32_t bh[2][4], bl[2][4];
            int bkrow = ks + ((lane >> 3) & 1) * 8 + (lane & 7);
            int bnc   = (lane >> 4) * 8;
#pragma unroll
            for (int pn = 0; pn < 2; pn++) {
                uint32_t bd = sb + so + ST_BHI + (uint32_t)(bkrow * BPITCH + wn * 32 + pn * 16 + bnc) * 2;
                ldmx4t(bh[pn], bd);
                ldmx4t(bl[pn], bd + (ST_BLO - ST_BHI));
            }
            int arow = ((lane >> 3) & 1) * 8 + (lane & 7);
            int akc  = ks + (lane >> 4) * 8;
#pragma unroll
            for (int mf = 0; mf < 4; mf++) {
                uint32_t ad = sb + so + ST_AHI + (uint32_t)((wm * 64 + mf * 16 + arow) * APITCH + akc) * 2;
                uint32_t ah[4], al[4];
                ldmx4(ah, ad);
                ldmx4(al, ad + ST_ALO);
#pragma unroll
                for (int nf = 0; nf < 4; nf++) {
                    int pn = nf >> 1, sub = nf & 1;
                    mma_bf16(acc[mf][nf], ah, bh[pn][sub * 2], bh[pn][sub * 2 + 1]);
                    mma_bf16(acc[mf][nf], ah, bl[pn][sub * 2], bl[pn][sub * 2 + 1]);
                    mma_bf16(acc[mf][nf], al, bh[pn][sub * 2], bh[pn][sub * 2 + 1]);
                }
            }
        }
        // node mode: convert staged A regs into next buffer (after compute; LDG latency hidden)
        if (mode == 0 && c + 1 < NC) {
            const float* vv = (const float*)stA;
            uint32_t ph[8], pl[8];
#pragma unroll
            for (int j = 0; j < 8; j++) {
                float f0 = vv[2 * j], f1 = vv[2 * j + 1];
                float h0 = __bfloat162float(__float2bfloat16_rn(f0));
                float h1 = __bfloat162float(__float2bfloat16_rn(f1));
                ph[j] = pack_bf(f0, f1);
                pl[j] = pack_bf(f0 - h0, f1 - h1);
            }
            *(int4*)(smc + no + aRel)               = *(int4*)&ph[0];
            *(int4*)(smc + no + aRel + 16)          = *(int4*)&ph[4];
            *(int4*)(smc + no + aRel + ST_ALO)      = *(int4*)&pl[0];
            *(int4*)(smc + no + aRel + ST_ALO + 16) = *(int4*)&pl[4];
        }
    }

    if (mode == 0) {
#pragma unroll
        for (int mf = 0; mf < 4; mf++) {
            int r0 = brow + wm * 64 + mf * 16 + gid;
#pragma unroll
            for (int nf = 0; nf < 4; nf++) {
                int col = bcol + wn * 32 + nf * 8 + 2 * tig;
                float b0 = bias[col], b1 = bias[col + 1];
                float v0 = acc[mf][nf][0] + b0;
                float v1 = acc[mf][nf][1] + b1;
                float v2 = acc[mf][nf][2] + b0;
                float v3 = acc[mf][nf][3] + b1;
                if (doRelu) {
                    v0 = fmaxf(v0, 0.f); v1 = fmaxf(v1, 0.f);
                    v2 = fmaxf(v2, 0.f); v3 = fmaxf(v3, 0.f);
                }
                if (r0 < M)     *(float2*)(out + (size_t)r0 * D_DIM + col)       = make_float2(v0, v1);
                if (r0 + 8 < M) *(float2*)(out + (size_t)(r0 + 8) * D_DIM + col) = make_float2(v2, v3);
            }
        }
    } else {
        __syncthreads();   // all warps done reading stage buffers before Cs overlay
#pragma unroll
        for (int mf = 0; mf < 4; mf++) {
            int rl = wm * 64 + mf * 16 + gid;
#pragma unroll
            for (int nf = 0; nf < 4; nf++) {
                int cl = wn * 32 + nf * 8 + 2 * tig;
                *(float2*)&Cs[rl * CPITCH + cl]       = make_float2(acc[mf][nf][0], acc[mf][nf][1]);
                *(float2*)&Cs[(rl + 8) * CPITCH + cl] = make_float2(acc[mf][nf][2], acc[mf][nf][3]);
            }
        }
        __syncthreads();
        // run-combined scatter: 8 consecutive sorted rows per thread
        int trow = (tid / 16) * 8;
        int tcol = (tid % 16) * 8;
        int colg = bcol + tcol;
        float bv[8];
        *(float4*)&bv[0] = *(const float4*)(bias + colg);
        *(float4*)&bv[4] = *(const float4*)(bias + colg + 4);
        float run[8];
        int prevDst = -1;
#pragma unroll
        for (int i = 0; i < 8; i++) {
            int r = brow + trow + i;
            int s = g_sortedSrc[r];
            int d = g_sortedDst[r];
            const float4* hp = (const float4*)(hbuf + (size_t)s * D_DIM + colg);
            float4 h0 = hp[0], h1 = hp[1];
            const float* cr = &Cs[(trow + i) * CPITCH + tcol];
            float m[8];
            m[0] = fmaxf(cr[0] + bv[0] + h0.x, 0.f);
            m[1] = fmaxf(cr[1] + bv[1] + h0.y, 0.f);
            m[2] = fmaxf(cr[2] + bv[2] + h0.z, 0.f);
            m[3] = fmaxf(cr[3] + bv[3] + h0.w, 0.f);
            m[4] = fmaxf(cr[4] + bv[4] + h1.x, 0.f);
            m[5] = fmaxf(cr[5] + bv[5] + h1.y, 0.f);
            m[6] = fmaxf(cr[6] + bv[6] + h1.z, 0.f);
            m[7] = fmaxf(cr[7] + bv[7] + h1.w, 0.f);
            if (d != prevDst) {
                if (prevDst >= 0) {
                    float* ap = out + (size_t)prevDst * D_DIM + colg;
#pragma unroll
                    for (int j = 0; j < 8; j++)
                        if (run[j] != 0.f) atomicAdd(&ap[j], run[j]);
                }
#pragma unroll
                for (int j = 0; j < 8; j++) run[j] = m[j];
                prevDst = d;
            } else {
#pragma unroll
                for (int j = 0; j < 8; j++) run[j] += m[j];
            }
        }
        if (prevDst >= 0) {
            float* ap = out + (size_t)prevDst * D_DIM + colg;
#pragma unroll
            for (int j = 0; j < 8; j++)
                if (run[j] != 0.f) atomicAdd(&ap[j], run[j]);
        }
    }
}

// ---------------- LayerNorm ----------------
__global__ void __launch_bounds__(128) layernorm_kernel(const float* __restrict__ g,
                                                        const float* __restrict__ gamma,
                                                        const float* __restrict__ beta,
                                                        float* __restrict__ out) {
    int row = blockIdx.x, t = threadIdx.x;
    const float4* gp = (const float4*)(g + (size_t)row * D_DIM);
    float4 v = gp[t];
    float s  = v.x + v.y + v.z + v.w;
    float sq = v.x * v.x + v.y * v.y + v.z * v.z + v.w * v.w;
#pragma unroll
    for (int o = 16; o > 0; o >>= 1) {
        s  += __shfl_xor_sync(0xffffffffu, s, o);
        sq += __shfl_xor_sync(0xffffffffu, sq, o);
    }
    __shared__ float red[8];
    int w = t >> 5;
    if ((t & 31) == 0) { red[w] = s; red[4 + w] = sq; }
    __syncthreads();
    s  = red[0] + red[1] + red[2] + red[3];
    sq = red[4] + red[5] + red[6] + red[7];
    float mu  = s * (1.0f / D_DIM);
    float var = sq * (1.0f / D_DIM) - mu * mu;
    float inv = rsqrtf(var + LN_EPS);
    float4 ga = *(const float4*)(gamma + t * 4);
    float4 be = *(const float4*)(beta + t * 4);
    float4 o;
    o.x = (v.x - mu) * inv * ga.x + be.x;
    o.y = (v.y - mu) * inv * ga.y + be.y;
    o.z = (v.z - mu) * inv * ga.z + be.z;
    o.w = (v.w - mu) * inv * ga.w + be.w;
    ((float4*)(out + (size_t)row * D_DIM))[t] = o;
}

// ---------------- launch ----------------
extern "C" void kernel_launch(void* const* d_in, const int* in_sizes, int n_in,
                              void* d_out, int out_size) {
    const float* x     = (const float*)d_in[0];
    const void*  ei    = d_in[1];
    const float* ea    = (const float*)d_in[2];
    const float* We    = (const float*)d_in[3];
    const float* be    = (const float*)d_in[4];
    const float* eps   = (const float*)d_in[5];
    const float* W1    = (const float*)d_in[6];
    const float* b1    = (const float*)d_in[7];
    const float* W2    = (const float*)d_in[8];
    const float* b2    = (const float*)d_in[9];
    const float* gamma = (const float*)d_in[10];
    const float* beta  = (const float*)d_in[11];
    const float* Wf    = (const float*)d_in[12];
    const float* bf    = (const float*)d_in[13];
    float* out = (float*)d_out;

    float *agg, *h, *t, *gg;
    __nv_bfloat16 *Wehi, *Welo, *W1hi, *W1lo, *W2hi, *W2lo, *Wfhi, *Wflo;
    cudaGetSymbolAddress((void**)&agg, g_agg);
    cudaGetSymbolAddress((void**)&h,   g_h);
    cudaGetSymbolAddress((void**)&t,   g_t);
    cudaGetSymbolAddress((void**)&gg,  g_g);
    cudaGetSymbolAddress((void**)&Wehi, g_Wehi);
    cudaGetSymbolAddress((void**)&Welo, g_Welo);
    cudaGetSymbolAddress((void**)&W1hi, g_W1hi);
    cudaGetSymbolAddress((void**)&W1lo, g_W1lo);
    cudaGetSymbolAddress((void**)&W2hi, g_W2hi);
    cudaGetSymbolAddress((void**)&W2lo, g_W2lo);
    cudaGetSymbolAddress((void**)&Wfhi, g_Wfhi);
    cudaGetSymbolAddress((void**)&Wflo, g_Wflo);

    cudaFuncSetAttribute(mma_fused_kernel, cudaFuncAttributeMaxDynamicSharedMemorySize, SMEM_TOTAL);

    // ---- preprocessing ----
    set_flag_kernel<<<1, 1>>>();
    detect_kernel<<<64, 256>>>((const long long*)ei);
    zero_pos_kernel<<<(N_NODES + 255) / 256, 256>>>();
    count_kernel<<<(E_EDGES + 255) / 256, 256>>>(ei);
    scan_kernel<<<1, 1024>>>();
    scatter_sort_kernel<<<(E_EDGES + 255) / 256, 256>>>(ei);

    int nthr = E_EDGES * (EDGE_DIM / 4);
    presplit_edges_kernel<<<(nthr + 255) / 256, 256>>>(ea);
    int we4 = L_LAYERS * EDGE_DIM * D_DIM / 4;
    int w4  = L_LAYERS * D_DIM * D_DIM / 4;
    int wf4 = D_DIM * D_DIM / 4;
    presplit_w_kernel<<<(we4 + 255) / 256, 256>>>(We, Wehi, Welo, we4);
    presplit_w_kernel<<<(w4 + 255) / 256, 256>>>(W1, W1hi, W1lo, w4);
    presplit_w_kernel<<<(w4 + 255) / 256, 256>>>(W2, W2hi, W2lo, w4);
    presplit_w_kernel<<<(wf4 + 255) / 256, 256>>>(Wf, Wfhi, Wflo, wf4);

    const int n4 = N_NODES * D_DIM / 4;
    dim3 gEdge(D_DIM / 128, E_EDGES / 128);           // (4, 1250)
    dim3 gNode(D_DIM / 128, (N_NODES + 127) / 128);   // (4, 79)
    const size_t WSTEP = (size_t)D_DIM * D_DIM;

    for (int l = 0; l < L_LAYERS; l++) {
        const float* hCur = (l == 0) ? x : h;
        scale_init_kernel<<<(n4 + 255) / 256, 256>>>((const float4*)hCur, eps, l, (float4*)agg, n4);
        mma_fused_kernel<<<gEdge, 256, SMEM_TOTAL>>>(
            nullptr, Wehi + (size_t)l * EDGE_DIM * D_DIM, Welo + (size_t)l * EDGE_DIM * D_DIM,
            be + (size_t)l * D_DIM, hCur, agg, E_EDGES, EDGE_DIM, 1, 0);
        mma_fused_kernel<<<gNode, 256, SMEM_TOTAL>>>(
            agg, W1hi + l * WSTEP, W1lo + l * WSTEP, b1 + (size_t)l * D_DIM,
            nullptr, t, N_NODES, D_DIM, 0, 1);
        mma_fused_kernel<<<gNode, 256, SMEM_TOTAL>>>(
            t, W2hi + l * WSTEP, W2lo + l * WSTEP, b2 + (size_t)l * D_DIM,
            nullptr, gg, N_NODES, D_DIM, 0, 1);
        layernorm_kernel<<<N_NODES, 128>>>(gg, gamma + (size_t)l * D_DIM,
                                           beta + (size_t)l * D_DIM, h);
    }
    mma_fused_kernel<<<gNode, 256, SMEM_TOTAL>>>(h, Wfhi, Wflo, bf, nullptr, out,
                                                 N_NODES, D_DIM, 0, 0);
}

// round 8
// speedup vs baseline: 2.8078x; 1.0119x over previous
#include <cuda_runtime.h>
#include <cuda_bf16.h>
#include <cstdint>

#define N_NODES   10000
#define E_EDGES   160000
#define D_DIM     512
#define EDGE_DIM  128
#define L_LAYERS  3
#define LN_EPS    1e-5f

// ---------------- scratch ----------------
__device__ __align__(16) float g_agg[(size_t)N_NODES * D_DIM];
__device__ __align__(16) float g_h  [(size_t)N_NODES * D_DIM];
__device__ __align__(16) float g_t  [(size_t)N_NODES * D_DIM];
__device__ __align__(16) float g_g  [(size_t)N_NODES * D_DIM];
__device__ __align__(16) __nv_bfloat16 g_EAhi[(size_t)E_EDGES * EDGE_DIM];
__device__ __align__(16) __nv_bfloat16 g_EAlo[(size_t)E_EDGES * EDGE_DIM];
__device__ __align__(16) __nv_bfloat16 g_Wehi[(size_t)L_LAYERS * EDGE_DIM * D_DIM];
__device__ __align__(16) __nv_bfloat16 g_Welo[(size_t)L_LAYERS * EDGE_DIM * D_DIM];
__device__ __align__(16) __nv_bfloat16 g_W1hi[(size_t)L_LAYERS * D_DIM * D_DIM];
__device__ __align__(16) __nv_bfloat16 g_W1lo[(size_t)L_LAYERS * D_DIM * D_DIM];
__device__ __align__(16) __nv_bfloat16 g_W2hi[(size_t)L_LAYERS * D_DIM * D_DIM];
__device__ __align__(16) __nv_bfloat16 g_W2lo[(size_t)L_LAYERS * D_DIM * D_DIM];
__device__ __align__(16) __nv_bfloat16 g_Wfhi[(size_t)D_DIM * D_DIM];
__device__ __align__(16) __nv_bfloat16 g_Wflo[(size_t)D_DIM * D_DIM];
__device__ int g_pos[N_NODES];
__device__ int g_perm[E_EDGES];
__device__ int g_sortedSrc[E_EDGES];
__device__ int g_sortedDst[E_EDGES];
__device__ int g_is64;

// ---------------- helpers ----------------
__device__ __forceinline__ uint32_t smem_u32(const void* p) {
    uint32_t a;
    asm("{ .reg .u64 t; cvta.to.shared.u64 t, %1; cvt.u32.u64 %0, t; }" : "=r"(a) : "l"(p));
    return a;
}
__device__ __forceinline__ uint32_t pack_bf(float a, float b) {
    uint32_t lo16 = __bfloat16_as_ushort(__float2bfloat16_rn(a));
    uint32_t hi16 = __bfloat16_as_ushort(__float2bfloat16_rn(b));
    return lo16 | (hi16 << 16);
}
__device__ __forceinline__ void ldmx4(uint32_t* r, uint32_t addr) {
    asm volatile("ldmatrix.sync.aligned.m8n8.x4.shared.b16 {%0,%1,%2,%3}, [%4];"
        : "=r"(r[0]), "=r"(r[1]), "=r"(r[2]), "=r"(r[3]) : "r"(addr));
}
__device__ __forceinline__ void ldmx4t(uint32_t* r, uint32_t addr) {
    asm volatile("ldmatrix.sync.aligned.m8n8.x4.trans.shared.b16 {%0,%1,%2,%3}, [%4];"
        : "=r"(r[0]), "=r"(r[1]), "=r"(r[2]), "=r"(r[3]) : "r"(addr));
}
__device__ __forceinline__ void mma_bf16(float* c, const uint32_t* a, uint32_t b0, uint32_t b1) {
    asm volatile("mma.sync.aligned.m16n8k16.row.col.f32.bf16.bf16.f32 "
        "{%0,%1,%2,%3}, {%4,%5,%6,%7}, {%8,%9}, {%0,%1,%2,%3};"
        : "+f"(c[0]), "+f"(c[1]), "+f"(c[2]), "+f"(c[3])
        : "r"(a[0]), "r"(a[1]), "r"(a[2]), "r"(a[3]), "r"(b0), "r"(b1));
}
__device__ __forceinline__ void cp16(uint32_t dst, const void* src) {
    asm volatile("cp.async.cg.shared.global [%0], [%1], 16;" :: "r"(dst), "l"(src));
}
__device__ __forceinline__ void cp_commit() { asm volatile("cp.async.commit_group;"); }
__device__ __forceinline__ void cp_wait0()  { asm volatile("cp.async.wait_group 0;"); }

// ---------------- dtype detection + counting sort ----------------
__global__ void detect_kernel(const long long* __restrict__ ei) {
    int idx = blockIdx.x * blockDim.x + threadIdx.x;
    if (idx == 0) g_is64 = 1;   // benign race: flag cleared below only after grid-wide check
    bool bad = false;
    for (int i = idx; i < E_EDGES; i += gridDim.x * blockDim.x) {
        long long v = ei[i];
        if (v < 0 || v >= N_NODES) bad = true;
    }
    if (__syncthreads_or(bad)) { if (threadIdx.x == 0) g_is64 = 0; }
}
__global__ void set_flag_kernel() { g_is64 = 1; }
__device__ __forceinline__ void get_edge(const void* ei, int e, int& s, int& d) {
    if (g_is64) {
        const long long* p = (const long long*)ei;
        s = (int)p[e]; d = (int)p[E_EDGES + e];
    } else {
        const int* p = (const int*)ei;
        s = p[e]; d = p[E_EDGES + e];
    }
}
__global__ void zero_pos_kernel() {
    int i = blockIdx.x * blockDim.x + threadIdx.x;
    if (i < N_NODES) g_pos[i] = 0;
}
__global__ void count_kernel(const void* __restrict__ ei) {
    int e = blockIdx.x * blockDim.x + threadIdx.x;
    if (e >= E_EDGES) return;
    int s, d; get_edge(ei, e, s, d);
    atomicAdd(&g_pos[d], 1);
}
__global__ void __launch_bounds__(1024) scan_kernel() {
    const int T = 1024, C = 10;
    __shared__ int sA[T], sB[T];
    int t = threadIdx.x, base = t * C, local[C], sum = 0;
#pragma unroll
    for (int c = 0; c < C; c++) {
        int i = base + c;
        local[c] = (i < N_NODES) ? g_pos[i] : 0;
        sum += local[c];
    }
    sA[t] = sum; __syncthreads();
    int* cur = sA; int* nxt = sB;
    for (int off = 1; off < T; off <<= 1) {
        int v = cur[t];
        if (t >= off) v += cur[t - off];
        nxt[t] = v; __syncthreads();
        int* tmp = cur; cur = nxt; nxt = tmp;
    }
    int running = (t > 0) ? cur[t - 1] : 0;
#pragma unroll
    for (int c = 0; c < C; c++) {
        int i = base + c;
        if (i < N_NODES) g_pos[i] = running;
        running += local[c];
    }
}
__global__ void scatter_sort_kernel(const void* __restrict__ ei) {
    int e = blockIdx.x * blockDim.x + threadIdx.x;
    if (e >= E_EDGES) return;
    int s, d; get_edge(ei, e, s, d);
    int pos = atomicAdd(&g_pos[d], 1);
    g_perm[pos] = e; g_sortedSrc[pos] = s; g_sortedDst[pos] = d;
}

// ---------------- pre-split kernels ----------------
__global__ void presplit_edges_kernel(const float* __restrict__ ea) {
    int idx = blockIdx.x * blockDim.x + threadIdx.x;
    if (idx >= E_EDGES * (EDGE_DIM / 4)) return;
    int p = idx >> 5;
    int c4 = (idx & 31) * 4;
    int e = g_perm[p];
    float4 v = *(const float4*)(ea + (size_t)e * EDGE_DIM + c4);
    float h0 = __bfloat162float(__float2bfloat16_rn(v.x));
    float h1 = __bfloat162float(__float2bfloat16_rn(v.y));
    float h2 = __bfloat162float(__float2bfloat16_rn(v.z));
    float h3 = __bfloat162float(__float2bfloat16_rn(v.w));
    uint2 ph, pl;
    ph.x = pack_bf(v.x, v.y); ph.y = pack_bf(v.z, v.w);
    pl.x = pack_bf(v.x - h0, v.y - h1); pl.y = pack_bf(v.z - h2, v.w - h3);
    *(uint2*)(g_EAhi + (size_t)p * EDGE_DIM + c4) = ph;
    *(uint2*)(g_EAlo + (size_t)p * EDGE_DIM + c4) = pl;
}
__global__ void presplit_w_kernel(const float* __restrict__ src, __nv_bfloat16* __restrict__ hi,
                                  __nv_bfloat16* __restrict__ lo, int n4) {
    int i = blockIdx.x * blockDim.x + threadIdx.x;
    if (i >= n4) return;
    float4 v = ((const float4*)src)[i];
    float h0 = __bfloat162float(__float2bfloat16_rn(v.x));
    float h1 = __bfloat162float(__float2bfloat16_rn(v.y));
    float h2 = __bfloat162float(__float2bfloat16_rn(v.z));
    float h3 = __bfloat162float(__float2bfloat16_rn(v.w));
    uint2 ph, pl;
    ph.x = pack_bf(v.x, v.y); ph.y = pack_bf(v.z, v.w);
    pl.x = pack_bf(v.x - h0, v.y - h1); pl.y = pack_bf(v.z - h2, v.w - h3);
    ((uint2*)hi)[i] = ph;
    ((uint2*)lo)[i] = pl;
}

// ---------------- agg = (1+eps[l]) * h (layer 0 only) ----------------
__global__ void scale_init_kernel(const float4* __restrict__ h, const float* __restrict__ eps,
                                  int l, float4* __restrict__ agg, int n4) {
    int i = blockIdx.x * blockDim.x + threadIdx.x;
    if (i >= n4) return;
    float s = 1.0f + eps[l];
    float4 v = h[i];
    v.x *= s; v.y *= s; v.z *= s; v.w *= s;
    agg[i] = v;
}

// ---------------- bf16x3 ldmatrix GEMM, cp.async double-buffered ----------------
#define APITCH 40
#define BPITCH 136
#define ST_AHI 0
#define ST_ALO (128 * APITCH * 2)
#define ST_BHI (2 * 128 * APITCH * 2)
#define ST_BLO (ST_BHI + 32 * BPITCH * 2)
#define STAGE_BYTES (ST_BLO + 32 * BPITCH * 2)  // 37888
#define SMEM_TOTAL (2 * STAGE_BYTES)            // 75776
#define CPITCH 136

template <int MODE>
__global__ void __launch_bounds__(256, 2) mma_fused_kernel(
        const float* __restrict__ A,
        const __nv_bfloat16* __restrict__ Bhi, const __nv_bfloat16* __restrict__ Blo,
        const float* __restrict__ bias, const float* __restrict__ hbuf,
        float* __restrict__ out, int M, int K, int doRelu) {
    extern __shared__ char smc[];
    uint32_t sb = smem_u32(smc);
    float* Cs = (float*)smc;

    int tid  = threadIdx.x;
    int wid  = tid >> 5;
    int lane = tid & 31;
    int gid  = lane >> 2;
    int tig  = lane & 3;
    int wm   = wid >> 2;
    int wn   = wid & 3;
    int brow = blockIdx.y * 128;
    int bcol = blockIdx.x * 128;

    float acc[4][4][4];
#pragma unroll
    for (int i = 0; i < 4; i++)
#pragma unroll
        for (int j = 0; j < 4; j++)
#pragma unroll
            for (int q = 0; q < 4; q++) acc[i][j][q] = 0.f;

    int aRow = tid >> 1, aSeg = tid & 1;
    int bKr  = tid >> 3, bSeg = tid & 7;
    const float* ApF = nullptr;
    const __nv_bfloat16 *ApHi = nullptr, *ApLo = nullptr;
    if (MODE == 1) {
        ApHi = g_EAhi + (size_t)(brow + aRow) * EDGE_DIM + aSeg * 16;
        ApLo = g_EAlo + (size_t)(brow + aRow) * EDGE_DIM + aSeg * 16;
    } else {
        int gr = brow + aRow;
        ApF = A + (size_t)(gr < M ? gr : 0) * K + aSeg * 16;
    }
    const __nv_bfloat16* BpHi = Bhi + (size_t)bKr * D_DIM + bcol + bSeg * 16;
    const __nv_bfloat16* BpLo = Blo + (size_t)bKr * D_DIM + bcol + bSeg * 16;
    uint32_t aRel = ST_AHI + (uint32_t)(aRow * APITCH + aSeg * 16) * 2;
    uint32_t bRel = ST_BHI + (uint32_t)(bKr * BPITCH + bSeg * 16) * 2;

    int NC = K >> 5;
    float4 stA[4];

    // ---- prologue: fill stage 0 ----
    {
        if (MODE == 1) {
            cp16(sb + aRel,                ApHi);
            cp16(sb + aRel + 16,           ApHi + 8);
            cp16(sb + aRel + ST_ALO,       ApLo);
            cp16(sb + aRel + ST_ALO + 16,  ApLo + 8);
        } else {
            stA[0] = *(const float4*)(ApF);
            stA[1] = *(const float4*)(ApF + 4);
            stA[2] = *(const float4*)(ApF + 8);
            stA[3] = *(const float4*)(ApF + 12);
        }
        cp16(sb + bRel,                              BpHi);
        cp16(sb + bRel + 16,                         BpHi + 8);
        cp16(sb + bRel + (ST_BLO - ST_BHI),          BpLo);
        cp16(sb + bRel + (ST_BLO - ST_BHI) + 16,     BpLo + 8);
        cp_commit();
        if (MODE == 0) {
            const float* vv = (const float*)stA;
            uint32_t ph[8], pl[8];
#pragma unroll
            for (int j = 0; j < 8; j++) {
                float f0 = vv[2 * j], f1 = vv[2 * j + 1];
                float h0 = __bfloat162float(__float2bfloat16_rn(f0));
                float h1 = __bfloat162float(__float2bfloat16_rn(f1));
                ph[j] = pack_bf(f0, f1);
                pl[j] = pack_bf(f0 - h0, f1 - h1);
            }
            *(int4*)(smc + aRel)               = *(int4*)&ph[0];
            *(int4*)(smc + aRel + 16)          = *(int4*)&ph[4];
            *(int4*)(smc + aRel + ST_ALO)      = *(int4*)&pl[0];
            *(int4*)(smc + aRel + ST_ALO + 16) = *(int4*)&pl[4];
        }
    }

    for (int c = 0; c < NC; c++) {
        uint32_t so = (c & 1) ? STAGE_BYTES : 0;
        uint32_t no = so ^ STAGE_BYTES;
        cp_wait0();
        __syncthreads();
        if (c + 1 < NC) {
            int k1 = (c + 1) * 32;
            if (MODE == 1) {
                cp16(sb + no + aRel,               ApHi + k1);
                cp16(sb + no + aRel + 16,          ApHi + k1 + 8);
                cp16(sb + no + aRel + ST_ALO,      ApLo + k1);
                cp16(sb + no + aRel + ST_ALO + 16, ApLo + k1 + 8);
            } else {
                stA[0] = *(const float4*)(ApF + k1);
                stA[1] = *(const float4*)(ApF + k1 + 4);
                stA[2] = *(const float4*)(ApF + k1 + 8);
                stA[3] = *(const float4*)(ApF + k1 + 12);
            }
            const __nv_bfloat16* bp = BpHi + (size_t)(c + 1) * 32 * D_DIM;
            const __nv_bfloat16* bq = BpLo + (size_t)(c + 1) * 32 * D_DIM;
            cp16(sb + no + bRel,                          bp);
            cp16(sb + no + bRel + 16,                     bp + 8);
            cp16(sb + no + bRel + (ST_BLO - ST_BHI),      bq);
            cp16(sb + no + bRel + (ST_BLO - ST_BHI) + 16, bq + 8);
            cp_commit();
        }
        // ---- compute: 2 k16 steps, product-major MMA order (dep distance 4) ----
#pragma unroll
        for (int ks = 0; ks < 32; ks += 16) {
            uint32_t bh[2][4], bl[2][4];
            int bkrow = ks + ((lane >> 3) & 1) * 8 + (lane & 7);
            int bnc   = (lane >> 4) * 8;
#pragma unroll
            for (int pn = 0; pn < 2; pn++) {
                uint32_t bd = sb + so + ST_BHI + (uint32_t)(bkrow * BPITCH + wn * 32 + pn * 16 + bnc) * 2;
                ldmx4t(bh[pn], bd);
                ldmx4t(bl[pn], bd + (ST_BLO - ST_BHI));
            }
            int arow = ((lane >> 3) & 1) * 8 + (lane & 7);
            int akc  = ks + (lane >> 4) * 8;
#pragma unroll
            for (int mf = 0; mf < 4; mf++) {
                uint32_t ad = sb + so + ST_AHI + (uint32_t)((wm * 64 + mf * 16 + arow) * APITCH + akc) * 2;
                uint32_t ah[4], al[4];
                ldmx4(ah, ad);
                ldmx4(al, ad + ST_ALO);
                // product 1: hi*hi over all nf
#pragma unroll
                for (int nf = 0; nf < 4; nf++) {
                    int pn = nf >> 1, sub = nf & 1;
                    mma_bf16(acc[mf][nf], ah, bh[pn][sub * 2], bh[pn][sub * 2 + 1]);
                }
                // product 2: hi*lo
#pragma unroll
                for (int nf = 0; nf < 4; nf++) {
                    int pn = nf >> 1, sub = nf & 1;
                    mma_bf16(acc[mf][nf], ah, bl[pn][sub * 2], bl[pn][sub * 2 + 1]);
                }
                // product 3: lo*hi
#pragma unroll
                for (int nf = 0; nf < 4; nf++) {
                    int pn = nf >> 1, sub = nf & 1;
                    mma_bf16(acc[mf][nf], al, bh[pn][sub * 2], bh[pn][sub * 2 + 1]);
                }
            }
        }
        if (MODE == 0 && c + 1 < NC) {
            const float* vv = (const float*)stA;
            uint32_t ph[8], pl[8];
#pragma unroll
            for (int j = 0; j < 8; j++) {
                float f0 = vv[2 * j], f1 = vv[2 * j + 1];
                float h0 = __bfloat162float(__float2bfloat16_rn(f0));
                float h1 = __bfloat162float(__float2bfloat16_rn(f1));
                ph[j] = pack_bf(f0, f1);
                pl[j] = pack_bf(f0 - h0, f1 - h1);
            }
            *(int4*)(smc + no + aRel)               = *(int4*)&ph[0];
            *(int4*)(smc + no + aRel + 16)          = *(int4*)&ph[4];
            *(int4*)(smc + no + aRel + ST_ALO)      = *(int4*)&pl[0];
            *(int4*)(smc + no + aRel + ST_ALO + 16) = *(int4*)&pl[4];
        }
    }

    if (MODE == 0) {
#pragma unroll
        for (int mf = 0; mf < 4; mf++) {
            int r0 = brow + wm * 64 + mf * 16 + gid;
#pragma unroll
            for (int nf = 0; nf < 4; nf++) {
                int col = bcol + wn * 32 + nf * 8 + 2 * tig;
                float b0 = bias[col], b1 = bias[col + 1];
                float v0 = acc[mf][nf][0] + b0;
                float v1 = acc[mf][nf][1] + b1;
                float v2 = acc[mf][nf][2] + b0;
                float v3 = acc[mf][nf][3] + b1;
                if (doRelu) {
                    v0 = fmaxf(v0, 0.f); v1 = fmaxf(v1, 0.f);
                    v2 = fmaxf(v2, 0.f); v3 = fmaxf(v3, 0.f);
                }
                if (r0 < M)     *(float2*)(out + (size_t)r0 * D_DIM + col)       = make_float2(v0, v1);
                if (r0 + 8 < M) *(float2*)(out + (size_t)(r0 + 8) * D_DIM + col) = make_float2(v2, v3);
            }
        }
    } else {
        __syncthreads();
#pragma unroll
        for (int mf = 0; mf < 4; mf++) {
            int rl = wm * 64 + mf * 16 + gid;
#pragma unroll
            for (int nf = 0; nf < 4; nf++) {
                int cl = wn * 32 + nf * 8 + 2 * tig;
                *(float2*)&Cs[rl * CPITCH + cl]       = make_float2(acc[mf][nf][0], acc[mf][nf][1]);
                *(float2*)&Cs[(rl + 8) * CPITCH + cl] = make_float2(acc[mf][nf][2], acc[mf][nf][3]);
            }
        }
        __syncthreads();
        int trow = (tid / 16) * 8;
        int tcol = (tid % 16) * 8;
        int colg = bcol + tcol;
        float bv[8];
        *(float4*)&bv[0] = *(const float4*)(bias + colg);
        *(float4*)&bv[4] = *(const float4*)(bias + colg + 4);
        float run[8];
        int prevDst = -1;
#pragma unroll
        for (int i = 0; i < 8; i++) {
            int r = brow + trow + i;
            int s = g_sortedSrc[r];
            int d = g_sortedDst[r];
            const float4* hp = (const float4*)(hbuf + (size_t)s * D_DIM + colg);
            float4 h0 = hp[0], h1 = hp[1];
            const float* cr = &Cs[(trow + i) * CPITCH + tcol];
            float m[8];
            m[0] = fmaxf(cr[0] + bv[0] + h0.x, 0.f);
            m[1] = fmaxf(cr[1] + bv[1] + h0.y, 0.f);
            m[2] = fmaxf(cr[2] + bv[2] + h0.z, 0.f);
            m[3] = fmaxf(cr[3] + bv[3] + h0.w, 0.f);
            m[4] = fmaxf(cr[4] + bv[4] + h1.x, 0.f);
            m[5] = fmaxf(cr[5] + bv[5] + h1.y, 0.f);
            m[6] = fmaxf(cr[6] + bv[6] + h1.z, 0.f);
            m[7] = fmaxf(cr[7] + bv[7] + h1.w, 0.f);
            if (d != prevDst) {
                if (prevDst >= 0) {
                    float* ap = out + (size_t)prevDst * D_DIM + colg;
#pragma unroll
                    for (int j = 0; j < 8; j++)
                        if (run[j] != 0.f) atomicAdd(&ap[j], run[j]);
                }
#pragma unroll
                for (int j = 0; j < 8; j++) run[j] = m[j];
                prevDst = d;
            } else {
#pragma unroll
                for (int j = 0; j < 8; j++) run[j] += m[j];
            }
        }
        if (prevDst >= 0) {
            float* ap = out + (size_t)prevDst * D_DIM + colg;
#pragma unroll
            for (int j = 0; j < 8; j++)
                if (run[j] != 0.f) atomicAdd(&ap[j], run[j]);
        }
    }
}

// ---------------- LayerNorm (+ fused agg init for next layer) ----------------
__global__ void __launch_bounds__(128) layernorm_kernel(const float* __restrict__ g,
                                                        const float* __restrict__ gamma,
                                                        const float* __restrict__ beta,
                                                        float* __restrict__ out,
                                                        const float* __restrict__ epsArr,
                                                        int nextLayer,      // <L: also write agg
                                                        float* __restrict__ agg) {
    int row = blockIdx.x, t = threadIdx.x;
    const float4* gp = (const float4*)(g + (size_t)row * D_DIM);
    float4 v = gp[t];
    float s  = v.x + v.y + v.z + v.w;
    float sq = v.x * v.x + v.y * v.y + v.z * v.z + v.w * v.w;
#pragma unroll
    for (int o = 16; o > 0; o >>= 1) {
        s  += __shfl_xor_sync(0xffffffffu, s, o);
        sq += __shfl_xor_sync(0xffffffffu, sq, o);
    }
    __shared__ float red[8];
    int w = t >> 5;
    if ((t & 31) == 0) { red[w] = s; red[4 + w] = sq; }
    __syncthreads();
    s  = red[0] + red[1] + red[2] + red[3];
    sq = red[4] + red[5] + red[6] + red[7];
    float mu  = s * (1.0f / D_DIM);
    float var = sq * (1.0f / D_DIM) - mu * mu;
    float inv = rsqrtf(var + LN_EPS);
    float4 ga = *(const float4*)(gamma + t * 4);
    float4 be = *(const float4*)(beta + t * 4);
    float4 o;
    o.x = (v.x - mu) * inv * ga.x + be.x;
    o.y = (v.y - mu) * inv * ga.y + be.y;
    o.z = (v.z - mu) * inv * ga.z + be.z;
    o.w = (v.w - mu) * inv * ga.w + be.w;
    ((float4*)(out + (size_t)row * D_DIM))[t] = o;
    if (nextLayer < L_LAYERS) {
        float sc = 1.0f + epsArr[nextLayer];
        float4 a;
        a.x = o.x * sc; a.y = o.y * sc; a.z = o.z * sc; a.w = o.w * sc;
        ((float4*)(agg + (size_t)row * D_DIM))[t] = a;
    }
}

// ---------------- launch ----------------
extern "C" void kernel_launch(void* const* d_in, const int* in_sizes, int n_in,
                              void* d_out, int out_size) {
    const float* x     = (const float*)d_in[0];
    const void*  ei    = d_in[1];
    const float* ea    = (const float*)d_in[2];
    const float* We    = (const float*)d_in[3];
    const float* be    = (const float*)d_in[4];
    const float* eps   = (const float*)d_in[5];
    const float* W1    = (const float*)d_in[6];
    const float* b1    = (const float*)d_in[7];
    const float* W2    = (const float*)d_in[8];
    const float* b2    = (const float*)d_in[9];
    const float* gamma = (const float*)d_in[10];
    const float* beta  = (const float*)d_in[11];
    const float* Wf    = (const float*)d_in[12];
    const float* bf    = (const float*)d_in[13];
    float* out = (float*)d_out;

    float *agg, *h, *t, *gg;
    __nv_bfloat16 *Wehi, *Welo, *W1hi, *W1lo, *W2hi, *W2lo, *Wfhi, *Wflo;
    cudaGetSymbolAddress((void**)&agg, g_agg);
    cudaGetSymbolAddress((void**)&h,   g_h);
    cudaGetSymbolAddress((void**)&t,   g_t);
    cudaGetSymbolAddress((void**)&gg,  g_g);
    cudaGetSymbolAddress((void**)&Wehi, g_Wehi);
    cudaGetSymbolAddress((void**)&Welo, g_Welo);
    cudaGetSymbolAddress((void**)&W1hi, g_W1hi);
    cudaGetSymbolAddress((void**)&W1lo, g_W1lo);
    cudaGetSymbolAddress((void**)&W2hi, g_W2hi);
    cudaGetSymbolAddress((void**)&W2lo, g_W2lo);
    cudaGetSymbolAddress((void**)&Wfhi, g_Wfhi);
    cudaGetSymbolAddress((void**)&Wflo, g_Wflo);

    cudaFuncSetAttribute(mma_fused_kernel<0>, cudaFuncAttributeMaxDynamicSharedMemorySize, SMEM_TOTAL);
    cudaFuncSetAttribute(mma_fused_kernel<1>, cudaFuncAttributeMaxDynamicSharedMemorySize, SMEM_TOTAL);

    // ---- preprocessing ----
    set_flag_kernel<<<1, 1>>>();
    detect_kernel<<<64, 256>>>((const long long*)ei);
    zero_pos_kernel<<<(N_NODES + 255) / 256, 256>>>();
    count_kernel<<<(E_EDGES + 255) / 256, 256>>>(ei);
    scan_kernel<<<1, 1024>>>();
    scatter_sort_kernel<<<(E_EDGES + 255) / 256, 256>>>(ei);

    int nthr = E_EDGES * (EDGE_DIM / 4);
    presplit_edges_kernel<<<(nthr + 255) / 256, 256>>>(ea);
    int we4 = L_LAYERS * EDGE_DIM * D_DIM / 4;
    int w4  = L_LAYERS * D_DIM * D_DIM / 4;
    int wf4 = D_DIM * D_DIM / 4;
    presplit_w_kernel<<<(we4 + 255) / 256, 256>>>(We, Wehi, Welo, we4);
    presplit_w_kernel<<<(w4 + 255) / 256, 256>>>(W1, W1hi, W1lo, w4);
    presplit_w_kernel<<<(w4 + 255) / 256, 256>>>(W2, W2hi, W2lo, w4);
    presplit_w_kernel<<<(wf4 + 255) / 256, 256>>>(Wf, Wfhi, Wflo, wf4);

    const int n4 = N_NODES * D_DIM / 4;
    dim3 gEdge(D_DIM / 128, E_EDGES / 128);
    dim3 gNode(D_DIM / 128, (N_NODES + 127) / 128);
    const size_t WSTEP = (size_t)D_DIM * D_DIM;

    // layer 0 agg init from x
    scale_init_kernel<<<(n4 + 255) / 256, 256>>>((const float4*)x, eps, 0, (float4*)agg, n4);

    for (int l = 0; l < L_LAYERS; l++) {
        const float* hCur = (l == 0) ? x : h;
        mma_fused_kernel<1><<<gEdge, 256, SMEM_TOTAL>>>(
            nullptr, Wehi + (size_t)l * EDGE_DIM * D_DIM, Welo + (size_t)l * EDGE_DIM * D_DIM,
            be + (size_t)l * D_DIM, hCur, agg, E_EDGES, EDGE_DIM, 0);
        mma_fused_kernel<0><<<gNode, 256, SMEM_TOTAL>>>(
            agg, W1hi + l * WSTEP, W1lo + l * WSTEP, b1 + (size_t)l * D_DIM,
            nullptr, t, N_NODES, D_DIM, 1);
        mma_fused_kernel<0><<<gNode, 256, SMEM_TOTAL>>>(
            t, W2hi + l * WSTEP, W2lo + l * WSTEP, b2 + (size_t)l * D_DIM,
            nullptr, gg, N_NODES, D_DIM, 1);
        // LN writes h AND (for l<L-1) agg = (1+eps[l+1])*h
        layernorm_kernel<<<N_NODES, 128>>>(gg, gamma + (size_t)l * D_DIM,
                                           beta + (size_t)l * D_DIM, h,
                                           eps, l + 1, agg);
    }
    mma_fused_kernel<0><<<gNode, 256, SMEM_TOTAL>>>(h, Wfhi, Wflo, bf, nullptr, out,
                                                    N_NODES, D_DIM, 0);
}

// round 9
// speedup vs baseline: 2.8361x; 1.0101x over previous
#include <cuda_runtime.h>
#include <cuda_bf16.h>
#include <cstdint>

#define N_NODES   10000
#define E_EDGES   160000
#define D_DIM     512
#define EDGE_DIM  128
#define L_LAYERS  3
#define LN_EPS    1e-5f

// ---------------- scratch ----------------
__device__ __align__(16) float g_agg[(size_t)N_NODES * D_DIM];
__device__ __align__(16) float g_h  [(size_t)N_NODES * D_DIM];
__device__ __align__(16) float g_t  [(size_t)N_NODES * D_DIM];
__device__ __align__(16) float g_g  [(size_t)N_NODES * D_DIM];
__device__ __align__(16) __nv_bfloat16 g_EAhi[(size_t)E_EDGES * EDGE_DIM];
__device__ __align__(16) __nv_bfloat16 g_EAlo[(size_t)E_EDGES * EDGE_DIM];
__device__ __align__(16) __nv_bfloat16 g_Wehi[(size_t)L_LAYERS * EDGE_DIM * D_DIM];
__device__ __align__(16) __nv_bfloat16 g_Welo[(size_t)L_LAYERS * EDGE_DIM * D_DIM];
__device__ __align__(16) __nv_bfloat16 g_W1hi[(size_t)L_LAYERS * D_DIM * D_DIM];
__device__ __align__(16) __nv_bfloat16 g_W1lo[(size_t)L_LAYERS * D_DIM * D_DIM];
__device__ __align__(16) __nv_bfloat16 g_W2hi[(size_t)L_LAYERS * D_DIM * D_DIM];
__device__ __align__(16) __nv_bfloat16 g_W2lo[(size_t)L_LAYERS * D_DIM * D_DIM];
__device__ __align__(16) __nv_bfloat16 g_Wfhi[(size_t)D_DIM * D_DIM];
__device__ __align__(16) __nv_bfloat16 g_Wflo[(size_t)D_DIM * D_DIM];
__device__ int g_pos[N_NODES];
__device__ int g_perm[E_EDGES];
__device__ int g_sortedSrc[E_EDGES];
__device__ int g_sortedDst[E_EDGES];
__device__ int g_is64 = 1;    // static init; detect only ever CLEARS it (monotonic, race-free)

// ---------------- helpers ----------------
__device__ __forceinline__ uint32_t smem_u32(const void* p) {
    uint32_t a;
    asm("{ .reg .u64 t; cvta.to.shared.u64 t, %1; cvt.u32.u64 %0, t; }" : "=r"(a) : "l"(p));
    return a;
}
__device__ __forceinline__ uint32_t pack_bf(float a, float b) {
    uint32_t lo16 = __bfloat16_as_ushort(__float2bfloat16_rn(a));
    uint32_t hi16 = __bfloat16_as_ushort(__float2bfloat16_rn(b));
    return lo16 | (hi16 << 16);
}
__device__ __forceinline__ void ldmx4(uint32_t* r, uint32_t addr) {
    asm volatile("ldmatrix.sync.aligned.m8n8.x4.shared.b16 {%0,%1,%2,%3}, [%4];"
        : "=r"(r[0]), "=r"(r[1]), "=r"(r[2]), "=r"(r[3]) : "r"(addr));
}
__device__ __forceinline__ void ldmx4t(uint32_t* r, uint32_t addr) {
    asm volatile("ldmatrix.sync.aligned.m8n8.x4.trans.shared.b16 {%0,%1,%2,%3}, [%4];"
        : "=r"(r[0]), "=r"(r[1]), "=r"(r[2]), "=r"(r[3]) : "r"(addr));
}
__device__ __forceinline__ void mma_bf16(float* c, const uint32_t* a, uint32_t b0, uint32_t b1) {
    asm volatile("mma.sync.aligned.m16n8k16.row.col.f32.bf16.bf16.f32 "
        "{%0,%1,%2,%3}, {%4,%5,%6,%7}, {%8,%9}, {%0,%1,%2,%3};"
        : "+f"(c[0]), "+f"(c[1]), "+f"(c[2]), "+f"(c[3])
        : "r"(a[0]), "r"(a[1]), "r"(a[2]), "r"(a[3]), "r"(b0), "r"(b1));
}
__device__ __forceinline__ void cp16(uint32_t dst, const void* src) {
    asm volatile("cp.async.cg.shared.global [%0], [%1], 16;" :: "r"(dst), "l"(src));
}
__device__ __forceinline__ void cp_commit() { asm volatile("cp.async.commit_group;"); }
__device__ __forceinline__ void cp_wait0()  { asm volatile("cp.async.wait_group 0;"); }

// ---------------- launch 0: dtype detect + zero g_pos ----------------
__global__ void detect_zero_kernel(const long long* __restrict__ ei) {
    int idx = blockIdx.x * blockDim.x + threadIdx.x;
    for (int i = idx; i < N_NODES; i += gridDim.x * blockDim.x) g_pos[i] = 0;
    bool bad = false;
    for (int i = idx; i < E_EDGES; i += gridDim.x * blockDim.x) {
        long long v = ei[i];
        if (v < 0 || v >= N_NODES) bad = true;
    }
    if (__syncthreads_or(bad)) { if (threadIdx.x == 0) g_is64 = 0; }
}
__device__ __forceinline__ void get_edge(const void* ei, int e, int& s, int& d) {
    if (g_is64) {
        const long long* p = (const long long*)ei;
        s = (int)p[e]; d = (int)p[E_EDGES + e];
    } else {
        const int* p = (const int*)ei;
        s = p[e]; d = p[E_EDGES + e];
    }
}
// ---------------- launch 1: count ----------------
__global__ void count_kernel(const void* __restrict__ ei) {
    int e = blockIdx.x * blockDim.x + threadIdx.x;
    if (e >= E_EDGES) return;
    int s, d; get_edge(ei, e, s, d);
    atomicAdd(&g_pos[d], 1);
}
// ---------------- launch 2: scan ----------------
__global__ void __launch_bounds__(1024) scan_kernel() {
    const int T = 1024, C = 10;
    __shared__ int sA[T], sB[T];
    int t = threadIdx.x, base = t * C, local[C], sum = 0;
#pragma unroll
    for (int c = 0; c < C; c++) {
        int i = base + c;
        local[c] = (i < N_NODES) ? g_pos[i] : 0;
        sum += local[c];
    }
    sA[t] = sum; __syncthreads();
    int* cur = sA; int* nxt = sB;
    for (int off = 1; off < T; off <<= 1) {
        int v = cur[t];
        if (t >= off) v += cur[t - off];
        nxt[t] = v; __syncthreads();
        int* tmp = cur; cur = nxt; nxt = tmp;
    }
    int running = (t > 0) ? cur[t - 1] : 0;
#pragma unroll
    for (int c = 0; c < C; c++) {
        int i = base + c;
        if (i < N_NODES) g_pos[i] = running;
        running += local[c];
    }
}
// ---------------- launch 3: scatter sort ----------------
__global__ void scatter_sort_kernel(const void* __restrict__ ei) {
    int e = blockIdx.x * blockDim.x + threadIdx.x;
    if (e >= E_EDGES) return;
    int s, d; get_edge(ei, e, s, d);
    int pos = atomicAdd(&g_pos[d], 1);
    g_perm[pos] = e; g_sortedSrc[pos] = s; g_sortedDst[pos] = d;
}

// ---------------- launch 4: mega presplit (edges + 4 weights + layer-0 agg init) ----------------
#define EDGE_BLKS (E_EDGES * (EDGE_DIM / 4) / 256)            // 20000
#define WE4 (L_LAYERS * EDGE_DIM * D_DIM / 4)                 // 49152
#define W4  (L_LAYERS * D_DIM * D_DIM / 4)                    // 196608
#define WF4 (D_DIM * D_DIM / 4)                               // 65536
#define N4  (N_NODES * D_DIM / 4)                             // 1280000
#define WE_BLKS (WE4 / 256)                                   // 192
#define W_BLKS  (W4 / 256)                                    // 768
#define WF_BLKS (WF4 / 256)                                   // 256
#define SC_BLKS ((N4 + 255) / 256)                            // 5000
#define MEGA_BLKS (EDGE_BLKS + WE_BLKS + 2 * W_BLKS + WF_BLKS + SC_BLKS)

__device__ __forceinline__ void split_store(float4 v, __nv_bfloat16* hi, __nv_bfloat16* lo, int i) {
    float h0 = __bfloat162float(__float2bfloat16_rn(v.x));
    float h1 = __bfloat162float(__float2bfloat16_rn(v.y));
    float h2 = __bfloat162float(__float2bfloat16_rn(v.z));
    float h3 = __bfloat162float(__float2bfloat16_rn(v.w));
    uint2 ph, pl;
    ph.x = pack_bf(v.x, v.y); ph.y = pack_bf(v.z, v.w);
    pl.x = pack_bf(v.x - h0, v.y - h1); pl.y = pack_bf(v.z - h2, v.w - h3);
    ((uint2*)hi)[i] = ph;
    ((uint2*)lo)[i] = pl;
}
__global__ void mega_presplit_kernel(const float* __restrict__ ea,
                                     const float* __restrict__ We,
                                     const float* __restrict__ W1,
                                     const float* __restrict__ W2,
                                     const float* __restrict__ Wf,
                                     const float* __restrict__ x,
                                     const float* __restrict__ eps,
                                     float* __restrict__ agg) {
    int b = blockIdx.x;
    int tid = threadIdx.x;
    if (b < EDGE_BLKS) {
        int idx = b * 256 + tid;                 // E*32 threads, 4 elems each
        int p = idx >> 5;
        int c4 = (idx & 31) * 4;
        int e = g_perm[p];
        float4 v = *(const float4*)(ea + (size_t)e * EDGE_DIM + c4);
        split_store(v, g_EAhi, g_EAlo, ((size_t)p * EDGE_DIM + c4) >> 2);
        return;
    }
    b -= EDGE_BLKS;
    if (b < WE_BLKS) {
        int i = b * 256 + tid;
        split_store(((const float4*)We)[i], g_Wehi, g_Welo, i);
        return;
    }
    b -= WE_BLKS;
    if (b < W_BLKS) {
        int i = b * 256 + tid;
        split_store(((const float4*)W1)[i], g_W1hi, g_W1lo, i);
        return;
    }
    b -= W_BLKS;
    if (b < W_BLKS) {
        int i = b * 256 + tid;
        split_store(((const float4*)W2)[i], g_W2hi, g_W2lo, i);
        return;
    }
    b -= W_BLKS;
    if (b < WF_BLKS) {
        int i = b * 256 + tid;
        split_store(((const float4*)Wf)[i], g_Wfhi, g_Wflo, i);
        return;
    }
    b -= WF_BLKS;
    {   // layer-0 agg init: agg = (1+eps[0]) * x
        int i = b * 256 + tid;
        if (i < N4) {
            float s = 1.0f + eps[0];
            float4 v = ((const float4*)x)[i];
            v.x *= s; v.y *= s; v.z *= s; v.w *= s;
            ((float4*)agg)[i] = v;
        }
    }
}

// ---------------- bf16x3 ldmatrix GEMM, cp.async double-buffered ----------------
#define APITCH 40
#define BPITCH 136
#define ST_AHI 0
#define ST_ALO (128 * APITCH * 2)
#define ST_BHI (2 * 128 * APITCH * 2)
#define ST_BLO (ST_BHI + 32 * BPITCH * 2)
#define STAGE_BYTES (ST_BLO + 32 * BPITCH * 2)  // 37888
#define SMEM_TOTAL (2 * STAGE_BYTES)            // 75776
#define CPITCH 136

template <int MODE>
__global__ void __launch_bounds__(256, 2) mma_fused_kernel(
        const float* __restrict__ A,
        const __nv_bfloat16* __restrict__ Bhi, const __nv_bfloat16* __restrict__ Blo,
        const float* __restrict__ bias, const float* __restrict__ hbuf,
        float* __restrict__ out, int M, int K, int doRelu) {
    extern __shared__ char smc[];
    uint32_t sb = smem_u32(smc);
    float* Cs = (float*)smc;

    int tid  = threadIdx.x;
    int wid  = tid >> 5;
    int lane = tid & 31;
    int gid  = lane >> 2;
    int tig  = lane & 3;
    int wm   = wid >> 2;
    int wn   = wid & 3;
    int brow = blockIdx.y * 128;
    int bcol = blockIdx.x * 128;

    float acc[4][4][4];
#pragma unroll
    for (int i = 0; i < 4; i++)
#pragma unroll
        for (int j = 0; j < 4; j++)
#pragma unroll
            for (int q = 0; q < 4; q++) acc[i][j][q] = 0.f;

    int aRow = tid >> 1, aSeg = tid & 1;
    int bKr  = tid >> 3, bSeg = tid & 7;
    const float* ApF = nullptr;
    const __nv_bfloat16 *ApHi = nullptr, *ApLo = nullptr;
    if (MODE == 1) {
        ApHi = g_EAhi + (size_t)(brow + aRow) * EDGE_DIM + aSeg * 16;
        ApLo = g_EAlo + (size_t)(brow + aRow) * EDGE_DIM + aSeg * 16;
    } else {
        int gr = brow + aRow;
        ApF = A + (size_t)(gr < M ? gr : 0) * K + aSeg * 16;
    }
    const __nv_bfloat16* BpHi = Bhi + (size_t)bKr * D_DIM + bcol + bSeg * 16;
    const __nv_bfloat16* BpLo = Blo + (size_t)bKr * D_DIM + bcol + bSeg * 16;
    uint32_t aRel = ST_AHI + (uint32_t)(aRow * APITCH + aSeg * 16) * 2;
    uint32_t bRel = ST_BHI + (uint32_t)(bKr * BPITCH + bSeg * 16) * 2;

    int NC = K >> 5;
    float4 stA[4];

    // ---- prologue: fill stage 0 ----
    {
        if (MODE == 1) {
            cp16(sb + aRel,                ApHi);
            cp16(sb + aRel + 16,           ApHi + 8);
            cp16(sb + aRel + ST_ALO,       ApLo);
            cp16(sb + aRel + ST_ALO + 16,  ApLo + 8);
        } else {
            stA[0] = *(const float4*)(ApF);
            stA[1] = *(const float4*)(ApF + 4);
            stA[2] = *(const float4*)(ApF + 8);
            stA[3] = *(const float4*)(ApF + 12);
        }
        cp16(sb + bRel,                              BpHi);
        cp16(sb + bRel + 16,                         BpHi + 8);
        cp16(sb + bRel + (ST_BLO - ST_BHI),          BpLo);
        cp16(sb + bRel + (ST_BLO - ST_BHI) + 16,     BpLo + 8);
        cp_commit();
        if (MODE == 0) {
            const float* vv = (const float*)stA;
            uint32_t ph[8], pl[8];
#pragma unroll
            for (int j = 0; j < 8; j++) {
                float f0 = vv[2 * j], f1 = vv[2 * j + 1];
                float h0 = __bfloat162float(__float2bfloat16_rn(f0));
                float h1 = __bfloat162float(__float2bfloat16_rn(f1));
                ph[j] = pack_bf(f0, f1);
                pl[j] = pack_bf(f0 - h0, f1 - h1);
            }
            *(int4*)(smc + aRel)               = *(int4*)&ph[0];
            *(int4*)(smc + aRel + 16)          = *(int4*)&ph[4];
            *(int4*)(smc + aRel + ST_ALO)      = *(int4*)&pl[0];
            *(int4*)(smc + aRel + ST_ALO + 16) = *(int4*)&pl[4];
        }
    }

    for (int c = 0; c < NC; c++) {
        uint32_t so = (c & 1) ? STAGE_BYTES : 0;
        uint32_t no = so ^ STAGE_BYTES;
        cp_wait0();
        __syncthreads();
        if (c + 1 < NC) {
            int k1 = (c + 1) * 32;
            if (MODE == 1) {
                cp16(sb + no + aRel,               ApHi + k1);
                cp16(sb + no + aRel + 16,          ApHi + k1 + 8);
                cp16(sb + no + aRel + ST_ALO,      ApLo + k1);
                cp16(sb + no + aRel + ST_ALO + 16, ApLo + k1 + 8);
            } else {
                stA[0] = *(const float4*)(ApF + k1);
                stA[1] = *(const float4*)(ApF + k1 + 4);
                stA[2] = *(const float4*)(ApF + k1 + 8);
                stA[3] = *(const float4*)(ApF + k1 + 12);
            }
            const __nv_bfloat16* bp = BpHi + (size_t)(c + 1) * 32 * D_DIM;
            const __nv_bfloat16* bq = BpLo + (size_t)(c + 1) * 32 * D_DIM;
            cp16(sb + no + bRel,                          bp);
            cp16(sb + no + bRel + 16,                     bp + 8);
            cp16(sb + no + bRel + (ST_BLO - ST_BHI),      bq);
            cp16(sb + no + bRel + (ST_BLO - ST_BHI) + 16, bq + 8);
            cp_commit();
        }
        // ---- compute: 2 k16 steps, product-major MMA order ----
#pragma unroll
        for (int ks = 0; ks < 32; ks += 16) {
            uint32_t bh[2][4], bl[2][4];
            int bkrow = ks + ((lane >> 3) & 1) * 8 + (lane & 7);
            int bnc   = (lane >> 4) * 8;
#pragma unroll
            for (int pn = 0; pn < 2; pn++) {
                uint32_t bd = sb + so + ST_BHI + (uint32_t)(bkrow * BPITCH + wn * 32 + pn * 16 + bnc) * 2;
                ldmx4t(bh[pn], bd);
                ldmx4t(bl[pn], bd + (ST_BLO - ST_BHI));
            }
            int arow = ((lane >> 3) & 1) * 8 + (lane & 7);
            int akc  = ks + (lane >> 4) * 8;
#pragma unroll
            for (int mf = 0; mf < 4; mf++) {
                uint32_t ad = sb + so + ST_AHI + (uint32_t)((wm * 64 + mf * 16 + arow) * APITCH + akc) * 2;
                uint32_t ah[4], al[4];
                ldmx4(ah, ad);
                ldmx4(al, ad + ST_ALO);
#pragma unroll
                for (int nf = 0; nf < 4; nf++) {
                    int pn = nf >> 1, sub = nf & 1;
                    mma_bf16(acc[mf][nf], ah, bh[pn][sub * 2], bh[pn][sub * 2 + 1]);
                }
#pragma unroll
                for (int nf = 0; nf < 4; nf++) {
                    int pn = nf >> 1, sub = nf & 1;
                    mma_bf16(acc[mf][nf], ah, bl[pn][sub * 2], bl[pn][sub * 2 + 1]);
                }
#pragma unroll
                for (int nf = 0; nf < 4; nf++) {
                    int pn = nf >> 1, sub = nf & 1;
                    mma_bf16(acc[mf][nf], al, bh[pn][sub * 2], bh[pn][sub * 2 + 1]);
                }
            }
        }
        if (MODE == 0 && c + 1 < NC) {
            const float* vv = (const float*)stA;
            uint32_t ph[8], pl[8];
#pragma unroll
            for (int j = 0; j < 8; j++) {
                float f0 = vv[2 * j], f1 = vv[2 * j + 1];
                float h0 = __bfloat162float(__float2bfloat16_rn(f0));
                float h1 = __bfloat162float(__float2bfloat16_rn(f1));
                ph[j] = pack_bf(f0, f1);
                pl[j] = pack_bf(f0 - h0, f1 - h1);
            }
            *(int4*)(smc + no + aRel)               = *(int4*)&ph[0];
            *(int4*)(smc + no + aRel + 16)          = *(int4*)&ph[4];
            *(int4*)(smc + no + aRel + ST_ALO)      = *(int4*)&pl[0];
            *(int4*)(smc + no + aRel + ST_ALO + 16) = *(int4*)&pl[4];
        }
    }

    if (MODE == 0) {
#pragma unroll
        for (int mf = 0; mf < 4; mf++) {
            int r0 = brow + wm * 64 + mf * 16 + gid;
#pragma unroll
            for (int nf = 0; nf < 4; nf++) {
                int col = bcol + wn * 32 + nf * 8 + 2 * tig;
                float b0 = bias[col], b1 = bias[col + 1];
                float v0 = acc[mf][nf][0] + b0;
                float v1 = acc[mf][nf][1] + b1;
                float v2 = acc[mf][nf][2] + b0;
                float v3 = acc[mf][nf][3] + b1;
                if (doRelu) {
                    v0 = fmaxf(v0, 0.f); v1 = fmaxf(v1, 0.f);
                    v2 = fmaxf(v2, 0.f); v3 = fmaxf(v3, 0.f);
                }
                if (r0 < M)     *(float2*)(out + (size_t)r0 * D_DIM + col)       = make_float2(v0, v1);
                if (r0 + 8 < M) *(float2*)(out + (size_t)(r0 + 8) * D_DIM + col) = make_float2(v2, v3);
            }
        }
    } else {
        __syncthreads();
#pragma unroll
        for (int mf = 0; mf < 4; mf++) {
            int rl = wm * 64 + mf * 16 + gid;
#pragma unroll
            for (int nf = 0; nf < 4; nf++) {
                int cl = wn * 32 + nf * 8 + 2 * tig;
                *(float2*)&Cs[rl * CPITCH + cl]       = make_float2(acc[mf][nf][0], acc[mf][nf][1]);
                *(float2*)&Cs[(rl + 8) * CPITCH + cl] = make_float2(acc[mf][nf][2], acc[mf][nf][3]);
            }
        }
        __syncthreads();
        int trow = (tid / 16) * 8;
        int tcol = (tid % 16) * 8;
        int colg = bcol + tcol;
        float bv[8];
        *(float4*)&bv[0] = *(const float4*)(bias + colg);
        *(float4*)&bv[4] = *(const float4*)(bias + colg + 4);
        float run[8];
        int prevDst = -1;
#pragma unroll
        for (int i = 0; i < 8; i++) {
            int r = brow + trow + i;
            int s = g_sortedSrc[r];
            int d = g_sortedDst[r];
            const float4* hp = (const float4*)(hbuf + (size_t)s * D_DIM + colg);
            float4 h0 = hp[0], h1 = hp[1];
            const float* cr = &Cs[(trow + i) * CPITCH + tcol];
            float m[8];
            m[0] = fmaxf(cr[0] + bv[0] + h0.x, 0.f);
            m[1] = fmaxf(cr[1] + bv[1] + h0.y, 0.f);
            m[2] = fmaxf(cr[2] + bv[2] + h0.z, 0.f);
            m[3] = fmaxf(cr[3] + bv[3] + h0.w, 0.f);
            m[4] = fmaxf(cr[4] + bv[4] + h1.x, 0.f);
            m[5] = fmaxf(cr[5] + bv[5] + h1.y, 0.f);
            m[6] = fmaxf(cr[6] + bv[6] + h1.z, 0.f);
            m[7] = fmaxf(cr[7] + bv[7] + h1.w, 0.f);
            if (d != prevDst) {
                if (prevDst >= 0) {
                    float* ap = out + (size_t)prevDst * D_DIM + colg;
#pragma unroll
                    for (int j = 0; j < 8; j++)
                        if (run[j] != 0.f) atomicAdd(&ap[j], run[j]);
                }
#pragma unroll
                for (int j = 0; j < 8; j++) run[j] = m[j];
                prevDst = d;
            } else {
#pragma unroll
                for (int j = 0; j < 8; j++) run[j] += m[j];
            }
        }
        if (prevDst >= 0) {
            float* ap = out + (size_t)prevDst * D_DIM + colg;
#pragma unroll
            for (int j = 0; j < 8; j++)
                if (run[j] != 0.f) atomicAdd(&ap[j], run[j]);
        }
    }
}

// ---------------- LayerNorm (+ fused agg init for next layer) ----------------
__global__ void __launch_bounds__(128) layernorm_kernel(const float* __restrict__ g,
                                                        const float* __restrict__ gamma,
                                                        const float* __restrict__ beta,
                                                        float* __restrict__ out,
                                                        const float* __restrict__ epsArr,
                                                        int nextLayer,
                                                        float* __restrict__ agg) {
    int row = blockIdx.x, t = threadIdx.x;
    const float4* gp = (const float4*)(g + (size_t)row * D_DIM);
    float4 v = gp[t];
    float s  = v.x + v.y + v.z + v.w;
    float sq = v.x * v.x + v.y * v.y + v.z * v.z + v.w * v.w;
#pragma unroll
    for (int o = 16; o > 0; o >>= 1) {
        s  += __shfl_xor_sync(0xffffffffu, s, o);
        sq += __shfl_xor_sync(0xffffffffu, sq, o);
    }
    __shared__ float red[8];
    int w = t >> 5;
    if ((t & 31) == 0) { red[w] = s; red[4 + w] = sq; }
    __syncthreads();
    s  = red[0] + red[1] + red[2] + red[3];
    sq = red[4] + red[5] + red[6] + red[7];
    float mu  = s * (1.0f / D_DIM);
    float var = sq * (1.0f / D_DIM) - mu * mu;
    float inv = rsqrtf(var + LN_EPS);
    float4 ga = *(const float4*)(gamma + t * 4);
    float4 be = *(const float4*)(beta + t * 4);
    float4 o;
    o.x = (v.x - mu) * inv * ga.x + be.x;
    o.y = (v.y - mu) * inv * ga.y + be.y;
    o.z = (v.z - mu) * inv * ga.z + be.z;
    o.w = (v.w - mu) * inv * ga.w + be.w;
    ((float4*)(out + (size_t)row * D_DIM))[t] = o;
    if (nextLayer < L_LAYERS) {
        float sc = 1.0f + epsArr[nextLayer];
        float4 a;
        a.x = o.x * sc; a.y = o.y * sc; a.z = o.z * sc; a.w = o.w * sc;
        ((float4*)(agg + (size_t)row * D_DIM))[t] = a;
    }
}

// ---------------- launch ----------------
extern "C" void kernel_launch(void* const* d_in, const int* in_sizes, int n_in,
                              void* d_out, int out_size) {
    const float* x     = (const float*)d_in[0];
    const void*  ei    = d_in[1];
    const float* ea    = (const float*)d_in[2];
    const float* We    = (const float*)d_in[3];
    const float* be    = (const float*)d_in[4];
    const float* eps   = (const float*)d_in[5];
    const float* W1    = (const float*)d_in[6];
    const float* b1    = (const float*)d_in[7];
    const float* W2    = (const float*)d_in[8];
    const float* b2    = (const float*)d_in[9];
    const float* gamma = (const float*)d_in[10];
    const float* beta  = (const float*)d_in[11];
    const float* Wf    = (const float*)d_in[12];
    const float* bf    = (const float*)d_in[13];
    float* out = (float*)d_out;

    float *agg, *h, *t, *gg;
    __nv_bfloat16 *Wehi, *Welo, *W1hi, *W1lo, *W2hi, *W2lo, *Wfhi, *Wflo;
    cudaGetSymbolAddress((void**)&agg, g_agg);
    cudaGetSymbolAddress((void**)&h,   g_h);
    cudaGetSymbolAddress((void**)&t,   g_t);
    cudaGetSymbolAddress((void**)&gg,  g_g);
    cudaGetSymbolAddress((void**)&Wehi, g_Wehi);
    cudaGetSymbolAddress((void**)&Welo, g_Welo);
    cudaGetSymbolAddress((void**)&W1hi, g_W1hi);
    cudaGetSymbolAddress((void**)&W1lo, g_W1lo);
    cudaGetSymbolAddress((void**)&W2hi, g_W2hi);
    cudaGetSymbolAddress((void**)&W2lo, g_W2lo);
    cudaGetSymbolAddress((void**)&Wfhi, g_Wfhi);
    cudaGetSymbolAddress((void**)&Wflo, g_Wflo);

    cudaFuncSetAttribute(mma_fused_kernel<0>, cudaFuncAttributeMaxDynamicSharedMemorySize, SMEM_TOTAL);
    cudaFuncSetAttribute(mma_fused_kernel<1>, cudaFuncAttributeMaxDynamicSharedMemorySize, SMEM_TOTAL);

    // ---- preprocessing: EXACTLY 5 launches before the first MMA (ncu -s 5 lands on edge mma) ----
    detect_zero_kernel<<<64, 256>>>((const long long*)ei);                 // launch 0
    count_kernel<<<(E_EDGES + 255) / 256, 256>>>(ei);                      // launch 1
    scan_kernel<<<1, 1024>>>();                                            // launch 2
    scatter_sort_kernel<<<(E_EDGES + 255) / 256, 256>>>(ei);               // launch 3
    mega_presplit_kernel<<<MEGA_BLKS, 256>>>(ea, We, W1, W2, Wf, x, eps, agg); // launch 4

    dim3 gEdge(D_DIM / 128, E_EDGES / 128);
    dim3 gNode(D_DIM / 128, (N_NODES + 127) / 128);
    const size_t WSTEP = (size_t)D_DIM * D_DIM;

    for (int l = 0; l < L_LAYERS; l++) {
        const float* hCur = (l == 0) ? x : h;
        mma_fused_kernel<1><<<gEdge, 256, SMEM_TOTAL>>>(                   // launch 5 = profiled
            nullptr, Wehi + (size_t)l * EDGE_DIM * D_DIM, Welo + (size_t)l * EDGE_DIM * D_DIM,
            be + (size_t)l * D_DIM, hCur, agg, E_EDGES, EDGE_DIM, 0);
        mma_fused_kernel<0><<<gNode, 256, SMEM_TOTAL>>>(
            agg, W1hi + l * WSTEP, W1lo + l * WSTEP, b1 + (size_t)l * D_DIM,
            nullptr, t, N_NODES, D_DIM, 1);
        mma_fused_kernel<0><<<gNode, 256, SMEM_TOTAL>>>(
            t, W2hi + l * WSTEP, W2lo + l * WSTEP, b2 + (size_t)l * D_DIM,
            nullptr, gg, N_NODES, D_DIM, 1);
        layernorm_kernel<<<N_NODES, 128>>>(gg, gamma + (size_t)l * D_DIM,
                                           beta + (size_t)l * D_DIM, h,
                                           eps, l + 1, agg);
    }
    mma_fused_kernel<0><<<gNode, 256, SMEM_TOTAL>>>(h, Wfhi, Wflo, bf, nullptr, out,
                                                    N_NODES, D_DIM, 0);
}